// round 1
// baseline (speedup 1.0000x reference)
#include <cuda_runtime.h>
#include <math.h>

// Problem constants
#define BATCH   2
#define S_LEN   2048
#define DIM_    2048
#define KVDIM   512
#define HD      64
#define NQH     32
#define GRP     4
#define M_ROWS  (BATCH * S_LEN)   // 4096

// ---------------------------------------------------------------------------
// Scratch: __device__ globals (allocation-free rule)
// ---------------------------------------------------------------------------
__device__ float g_Q[(size_t)M_ROWS * DIM_];    // 32 MB
__device__ float g_K[(size_t)M_ROWS * KVDIM];   //  8 MB
__device__ float g_V[(size_t)M_ROWS * KVDIM];   //  8 MB
__device__ float g_O[(size_t)M_ROWS * DIM_];    // 32 MB

// ---------------------------------------------------------------------------
// SGEMM: C[M,N] = A[M,K] @ B[K,N], row-major fp32.
// Requires M%128==0, N%128==0, K%16==0 (true for all uses here).
// 256 threads, 128x128 block tile, 16 k-tile, 8x8 per-thread register tile.
// ---------------------------------------------------------------------------
__global__ __launch_bounds__(256) void sgemm128(
    const float* __restrict__ A, const float* __restrict__ B,
    float* __restrict__ C, int M, int N, int K)
{
    __shared__ float As[16][128];   // transposed A tile: As[k][m]
    __shared__ float Bs[16][128];   // Bs[k][n]

    const int tid = threadIdx.x;
    const int tx  = tid & 15;       // 0..15 -> n
    const int ty  = tid >> 4;       // 0..15 -> m
    const int bm  = blockIdx.y * 128;
    const int bn  = blockIdx.x * 128;

    const int aRow = tid >> 2;            // 0..63
    const int aCol = (tid & 3) << 2;      // 0,4,8,12
    const int bRow = tid >> 5;            // 0..7
    const int bCol = (tid & 31) << 2;     // 0..124

    float acc[8][8];
    #pragma unroll
    for (int i = 0; i < 8; i++)
        #pragma unroll
        for (int j = 0; j < 8; j++) acc[i][j] = 0.0f;

    for (int k0 = 0; k0 < K; k0 += 16) {
        #pragma unroll
        for (int h = 0; h < 2; h++) {
            int r = aRow + h * 64;
            float4 a = *(const float4*)&A[(size_t)(bm + r) * K + k0 + aCol];
            As[aCol + 0][r] = a.x;
            As[aCol + 1][r] = a.y;
            As[aCol + 2][r] = a.z;
            As[aCol + 3][r] = a.w;
        }
        #pragma unroll
        for (int h = 0; h < 2; h++) {
            int r = bRow + h * 8;
            *(float4*)&Bs[r][bCol] =
                *(const float4*)&B[(size_t)(k0 + r) * N + bn + bCol];
        }
        __syncthreads();

        #pragma unroll
        for (int kk = 0; kk < 16; kk++) {
            float ar[8], br[8];
            #pragma unroll
            for (int i = 0; i < 8; i++) ar[i] = As[kk][ty * 8 + i];
            #pragma unroll
            for (int j = 0; j < 8; j++) br[j] = Bs[kk][tx * 8 + j];
            #pragma unroll
            for (int i = 0; i < 8; i++)
                #pragma unroll
                for (int j = 0; j < 8; j++)
                    acc[i][j] = fmaf(ar[i], br[j], acc[i][j]);
        }
        __syncthreads();
    }

    #pragma unroll
    for (int i = 0; i < 8; i++) {
        float* crow = &C[(size_t)(bm + ty * 8 + i) * N + bn + tx * 8];
        *(float4*)&crow[0] = make_float4(acc[i][0], acc[i][1], acc[i][2], acc[i][3]);
        *(float4*)&crow[4] = make_float4(acc[i][4], acc[i][5], acc[i][6], acc[i][7]);
    }
}

// ---------------------------------------------------------------------------
// Flash attention, non-causal, D=64, 64x64 tiles, fp32.
// Grid: (S/64, NQH, BATCH). 256 threads as 16x16, each owns 4x4 of the tile.
// Q layout: [B,S,DIM] where DIM = (kv_head, group, head_dim) flattened.
// K/V layout: [B,S,KVDIM] where KVDIM = (kv_head, head_dim).
// ---------------------------------------------------------------------------
#define PAD 68
#define FLASH_SMEM (4 * 64 * PAD * 4)   // Qs,Ks,Vs,Ps = 69632 bytes

__global__ __launch_bounds__(256) void flash64(
    const float* __restrict__ Q, const float* __restrict__ K,
    const float* __restrict__ V, float* __restrict__ O)
{
    extern __shared__ float sm[];
    float* Qs = sm;
    float* Ks = Qs + 64 * PAD;
    float* Vs = Ks + 64 * PAD;
    float* Ps = Vs + 64 * PAD;

    const int tid = threadIdx.x;
    const int tx  = tid & 15;    // -> k-col group of 4
    const int ty  = tid >> 4;    // -> q-row group of 4
    const int qt  = blockIdx.x;  // q tile 0..31
    const int qh  = blockIdx.y;  // q head 0..31
    const int b   = blockIdx.z;
    const int kvh = qh >> 2;     // q head h = kv*GRP + g
    const float sm_scale = 0.125f;  // 1/sqrt(64)

    const float* Qg = Q + ((size_t)(b * S_LEN + qt * 64)) * DIM_ + qh * HD;
    const float* Kg = K + ((size_t)b * S_LEN) * KVDIM + kvh * HD;
    const float* Vg = V + ((size_t)b * S_LEN) * KVDIM + kvh * HD;
    float*       Og = O + ((size_t)(b * S_LEN + qt * 64)) * DIM_ + qh * HD;

    // Load Q tile 64x64 (each thread: 4 float4 of one row segment)
    {
        int r = tid >> 2;
        int c = (tid & 3) * 16;
        #pragma unroll
        for (int u = 0; u < 4; u++)
            *(float4*)&Qs[r * PAD + c + u * 4] =
                *(const float4*)&Qg[(size_t)r * DIM_ + c + u * 4];
    }

    const int r0 = ty * 4;
    const int c0 = tx * 4;

    float m_i[4], l_i[4], oacc[4][4];
    #pragma unroll
    for (int i = 0; i < 4; i++) {
        m_i[i] = -1e30f; l_i[i] = 0.0f;
        #pragma unroll
        for (int j = 0; j < 4; j++) oacc[i][j] = 0.0f;
    }

    const int lr = tid >> 2;           // load row 0..63
    const int lc = (tid & 3) * 16;     // load col 0,16,32,48

    for (int kt = 0; kt < S_LEN / 64; kt++) {
        // Load K and V tiles
        #pragma unroll
        for (int u = 0; u < 4; u++) {
            *(float4*)&Ks[lr * PAD + lc + u * 4] =
                *(const float4*)&Kg[(size_t)(kt * 64 + lr) * KVDIM + lc + u * 4];
            *(float4*)&Vs[lr * PAD + lc + u * 4] =
                *(const float4*)&Vg[(size_t)(kt * 64 + lr) * KVDIM + lc + u * 4];
        }
        __syncthreads();

        // Scores: s[i][j] = Q[r0+i,:] . K[c0+j,:]
        float s[4][4];
        #pragma unroll
        for (int i = 0; i < 4; i++)
            #pragma unroll
            for (int j = 0; j < 4; j++) s[i][j] = 0.0f;

        #pragma unroll
        for (int d4 = 0; d4 < 16; d4++) {
            float4 qv[4], kv4[4];
            #pragma unroll
            for (int i = 0; i < 4; i++)
                qv[i] = *(float4*)&Qs[(r0 + i) * PAD + d4 * 4];
            #pragma unroll
            for (int j = 0; j < 4; j++)
                kv4[j] = *(float4*)&Ks[(c0 + j) * PAD + d4 * 4];
            #pragma unroll
            for (int i = 0; i < 4; i++)
                #pragma unroll
                for (int j = 0; j < 4; j++) {
                    s[i][j] = fmaf(qv[i].x, kv4[j].x, s[i][j]);
                    s[i][j] = fmaf(qv[i].y, kv4[j].y, s[i][j]);
                    s[i][j] = fmaf(qv[i].z, kv4[j].z, s[i][j]);
                    s[i][j] = fmaf(qv[i].w, kv4[j].w, s[i][j]);
                }
        }

        // Online softmax per row (row shared by 16 tx-threads; tx = lane%16)
        #pragma unroll
        for (int i = 0; i < 4; i++) {
            #pragma unroll
            for (int j = 0; j < 4; j++) s[i][j] *= sm_scale;

            float rmax = fmaxf(fmaxf(s[i][0], s[i][1]), fmaxf(s[i][2], s[i][3]));
            #pragma unroll
            for (int o = 8; o >= 1; o >>= 1)
                rmax = fmaxf(rmax, __shfl_xor_sync(0xffffffffu, rmax, o));

            float mnew  = fmaxf(m_i[i], rmax);
            float alpha = __expf(m_i[i] - mnew);
            float rsum  = 0.0f;
            #pragma unroll
            for (int j = 0; j < 4; j++) {
                float p = __expf(s[i][j] - mnew);
                s[i][j] = p;
                rsum += p;
            }
            #pragma unroll
            for (int o = 8; o >= 1; o >>= 1)
                rsum += __shfl_xor_sync(0xffffffffu, rsum, o);

            l_i[i] = l_i[i] * alpha + rsum;
            m_i[i] = mnew;
            #pragma unroll
            for (int j = 0; j < 4; j++) oacc[i][j] *= alpha;

            *(float4*)&Ps[(r0 + i) * PAD + c0] =
                make_float4(s[i][0], s[i][1], s[i][2], s[i][3]);
        }
        __syncthreads();

        // O += P @ V  (oacc[i][j] over kk)
        #pragma unroll 8
        for (int kk = 0; kk < 64; kk++) {
            float4 vv = *(float4*)&Vs[kk * PAD + c0];
            float p0 = Ps[(r0 + 0) * PAD + kk];
            float p1 = Ps[(r0 + 1) * PAD + kk];
            float p2 = Ps[(r0 + 2) * PAD + kk];
            float p3 = Ps[(r0 + 3) * PAD + kk];
            oacc[0][0] = fmaf(p0, vv.x, oacc[0][0]); oacc[0][1] = fmaf(p0, vv.y, oacc[0][1]);
            oacc[0][2] = fmaf(p0, vv.z, oacc[0][2]); oacc[0][3] = fmaf(p0, vv.w, oacc[0][3]);
            oacc[1][0] = fmaf(p1, vv.x, oacc[1][0]); oacc[1][1] = fmaf(p1, vv.y, oacc[1][1]);
            oacc[1][2] = fmaf(p1, vv.z, oacc[1][2]); oacc[1][3] = fmaf(p1, vv.w, oacc[1][3]);
            oacc[2][0] = fmaf(p2, vv.x, oacc[2][0]); oacc[2][1] = fmaf(p2, vv.y, oacc[2][1]);
            oacc[2][2] = fmaf(p2, vv.z, oacc[2][2]); oacc[2][3] = fmaf(p2, vv.w, oacc[2][3]);
            oacc[3][0] = fmaf(p3, vv.x, oacc[3][0]); oacc[3][1] = fmaf(p3, vv.y, oacc[3][1]);
            oacc[3][2] = fmaf(p3, vv.z, oacc[3][2]); oacc[3][3] = fmaf(p3, vv.w, oacc[3][3]);
        }
        __syncthreads();
    }

    // Normalize and write out
    #pragma unroll
    for (int i = 0; i < 4; i++) {
        float inv = 1.0f / l_i[i];
        *(float4*)&Og[(size_t)(r0 + i) * DIM_ + c0] =
            make_float4(oacc[i][0] * inv, oacc[i][1] * inv,
                        oacc[i][2] * inv, oacc[i][3] * inv);
    }
}

// ---------------------------------------------------------------------------
// Launch: x@Wq, x@Wk, x@Wv -> flash attention -> O@Wo
// ---------------------------------------------------------------------------
extern "C" void kernel_launch(void* const* d_in, const int* in_sizes, int n_in,
                              void* d_out, int out_size) {
    (void)in_sizes; (void)n_in; (void)out_size;
    const float* x  = (const float*)d_in[0];
    const float* Wq = (const float*)d_in[1];
    const float* Wk = (const float*)d_in[2];
    const float* Wv = (const float*)d_in[3];
    const float* Wo = (const float*)d_in[4];
    float* out = (float*)d_out;

    float *Qp, *Kp, *Vp, *Op;
    cudaGetSymbolAddress((void**)&Qp, g_Q);
    cudaGetSymbolAddress((void**)&Kp, g_K);
    cudaGetSymbolAddress((void**)&Vp, g_V);
    cudaGetSymbolAddress((void**)&Op, g_O);

    cudaFuncSetAttribute(flash64, cudaFuncAttributeMaxDynamicSharedMemorySize,
                         FLASH_SMEM);

    dim3 blk(256);
    // Projections
    sgemm128<<<dim3(DIM_ / 128, M_ROWS / 128), blk>>>(x, Wq, Qp, M_ROWS, DIM_, DIM_);
    sgemm128<<<dim3(KVDIM / 128, M_ROWS / 128), blk>>>(x, Wk, Kp, M_ROWS, KVDIM, DIM_);
    sgemm128<<<dim3(KVDIM / 128, M_ROWS / 128), blk>>>(x, Wv, Vp, M_ROWS, KVDIM, DIM_);
    // Attention
    flash64<<<dim3(S_LEN / 64, NQH, BATCH), blk, FLASH_SMEM>>>(Qp, Kp, Vp, Op);
    // Output projection
    sgemm128<<<dim3(DIM_ / 128, M_ROWS / 128), blk>>>(Op, Wo, out, M_ROWS, DIM_, DIM_);
}

// round 2
// speedup vs baseline: 4.1731x; 4.1731x over previous
#include <cuda_runtime.h>
#include <math.h>
#include <stdint.h>

// Problem constants
#define BATCH   2
#define S_LEN   2048
#define DIM_    2048
#define KVDIM   512
#define HD      64
#define NQH     32
#define M_ROWS  (BATCH * S_LEN)   // 4096

// ---------------------------------------------------------------------------
// Scratch
// ---------------------------------------------------------------------------
__device__ float g_Q[(size_t)M_ROWS * DIM_];
__device__ float g_K[(size_t)M_ROWS * KVDIM];
__device__ float g_V[(size_t)M_ROWS * KVDIM];
__device__ float g_O[(size_t)M_ROWS * DIM_];

// ---------------------------------------------------------------------------
// TF32 helpers
// ---------------------------------------------------------------------------
__device__ __forceinline__ float tf32f(float x) {
    uint32_t u;
    asm("cvt.rna.tf32.f32 %0, %1;" : "=r"(u) : "f"(x));
    return __uint_as_float(u);
}

__device__ __forceinline__ void mma_tf32(float c[4],
    uint32_t a0, uint32_t a1, uint32_t a2, uint32_t a3,
    uint32_t b0, uint32_t b1)
{
    asm volatile(
        "mma.sync.aligned.m16n8k8.row.col.f32.tf32.tf32.f32 "
        "{%0,%1,%2,%3}, {%4,%5,%6,%7}, {%8,%9}, {%0,%1,%2,%3};"
        : "+f"(c[0]), "+f"(c[1]), "+f"(c[2]), "+f"(c[3])
        : "r"(a0), "r"(a1), "r"(a2), "r"(a3), "r"(b0), "r"(b1));
}

// ---------------------------------------------------------------------------
// TF32 MMA GEMM: C[M,N] = A[M,K] @ B[K,N], row-major fp32 in/out.
// 128x128 block tile, BK=32, 256 threads = 8 warps (2m x 4n), warp tile 64x32.
// ---------------------------------------------------------------------------
#define GAS 36    // As row stride (4m+k banks -> conflict-free frag loads)
#define GBS 136   // Bs row stride (8k+n banks -> conflict-free frag loads)

__global__ __launch_bounds__(256) void mma_gemm(
    const float* __restrict__ A, const float* __restrict__ B,
    float* __restrict__ C, int M, int N, int K)
{
    __shared__ float As[128 * GAS];
    __shared__ float Bs[32 * GBS];

    const int tid    = threadIdx.x;
    const int lane   = tid & 31;
    const int warpid = tid >> 5;
    const int wm     = (warpid >> 2) * 64;   // warp row offset (0 or 64)
    const int wn     = (warpid & 3) * 32;    // warp col offset
    const int bm     = blockIdx.y * 128;
    const int bn     = blockIdx.x * 128;
    const int g      = lane >> 2;            // groupID 0..7
    const int t      = lane & 3;             // threadID_in_group 0..3

    float acc[4][4][4];
    #pragma unroll
    for (int i = 0; i < 4; i++)
        #pragma unroll
        for (int j = 0; j < 4; j++)
            #pragma unroll
            for (int r = 0; r < 4; r++) acc[i][j][r] = 0.0f;

    for (int k0 = 0; k0 < K; k0 += 32) {
        // Stage A (128x32) row-major, tf32-converted
        #pragma unroll
        for (int h = 0; h < 4; h++) {
            int idx = tid + 256 * h;         // 0..1023 float4s
            int row = idx >> 3;
            int c4  = (idx & 7) * 4;
            float4 a = *(const float4*)&A[(size_t)(bm + row) * K + k0 + c4];
            float4 s = make_float4(tf32f(a.x), tf32f(a.y), tf32f(a.z), tf32f(a.w));
            *(float4*)&As[row * GAS + c4] = s;
        }
        // Stage B (32x128) row-major, tf32-converted
        #pragma unroll
        for (int h = 0; h < 4; h++) {
            int idx = tid + 256 * h;
            int row = idx >> 5;
            int c4  = (idx & 31) * 4;
            float4 b = *(const float4*)&B[(size_t)(k0 + row) * N + bn + c4];
            float4 s = make_float4(tf32f(b.x), tf32f(b.y), tf32f(b.z), tf32f(b.w));
            *(float4*)&Bs[row * GBS + c4] = s;
        }
        __syncthreads();

        #pragma unroll
        for (int ks = 0; ks < 4; ks++) {
            const int kb = ks * 8;
            uint32_t af[4][4], bf[4][2];
            #pragma unroll
            for (int mt = 0; mt < 4; mt++) {
                int m0 = wm + mt * 16;
                af[mt][0] = __float_as_uint(As[(m0 + g) * GAS + kb + t]);
                af[mt][1] = __float_as_uint(As[(m0 + g + 8) * GAS + kb + t]);
                af[mt][2] = __float_as_uint(As[(m0 + g) * GAS + kb + t + 4]);
                af[mt][3] = __float_as_uint(As[(m0 + g + 8) * GAS + kb + t + 4]);
            }
            #pragma unroll
            for (int nt = 0; nt < 4; nt++) {
                int n0 = wn + nt * 8;
                bf[nt][0] = __float_as_uint(Bs[(kb + t) * GBS + n0 + g]);
                bf[nt][1] = __float_as_uint(Bs[(kb + t + 4) * GBS + n0 + g]);
            }
            #pragma unroll
            for (int mt = 0; mt < 4; mt++)
                #pragma unroll
                for (int nt = 0; nt < 4; nt++)
                    mma_tf32(acc[mt][nt], af[mt][0], af[mt][1], af[mt][2], af[mt][3],
                             bf[nt][0], bf[nt][1]);
        }
        __syncthreads();
    }

    // Epilogue
    #pragma unroll
    for (int mt = 0; mt < 4; mt++) {
        int row0 = bm + wm + mt * 16 + g;
        #pragma unroll
        for (int nt = 0; nt < 4; nt++) {
            int col = bn + wn + nt * 8 + 2 * t;
            *(float2*)&C[(size_t)row0 * N + col] =
                make_float2(acc[mt][nt][0], acc[mt][nt][1]);
            *(float2*)&C[(size_t)(row0 + 8) * N + col] =
                make_float2(acc[mt][nt][2], acc[mt][nt][3]);
        }
    }
}

// ---------------------------------------------------------------------------
// Flash attention with tf32 MMA. D=64, 64x64 tiles.
// 128 threads = 4 warps; warp w owns q rows [16w,16w+16).
// Grid: (S/64, NQH, BATCH).
// ---------------------------------------------------------------------------
#define KS_STR 68   // Ks/Qs stride: banks (4m+k) conflict-free
#define VS_STR 72   // Vs stride:   banks (8k+n) conflict-free
#define PS_STR 68   // Ps stride:   banks (4m+k) conflict-free

#define SM_KS   0
#define SM_VS   (64 * KS_STR)
#define SM_PS   (SM_VS + 64 * VS_STR)
#define FLASH_FLOATS (SM_PS + 4 * 16 * PS_STR)
#define FLASH_SMEM   (FLASH_FLOATS * 4)

__global__ __launch_bounds__(128) void flash_mma(
    const float* __restrict__ Q, const float* __restrict__ K,
    const float* __restrict__ V, float* __restrict__ O)
{
    extern __shared__ float sm[];
    float* Ks = sm + SM_KS;   // K chunk (aliases Q staging)
    float* Vs = sm + SM_VS;
    float* Ps = sm + SM_PS;

    const int tid    = threadIdx.x;
    const int lane   = tid & 31;
    const int warpid = tid >> 5;
    const int g      = lane >> 2;
    const int t      = lane & 3;
    const int qt     = blockIdx.x;
    const int qh     = blockIdx.y;
    const int b      = blockIdx.z;
    const int kvh    = qh >> 2;
    const float sm_scale = 0.125f;

    const float* Qg = Q + ((size_t)(b * S_LEN + qt * 64)) * DIM_ + qh * HD;
    const float* Kg = K + ((size_t)b * S_LEN) * KVDIM + kvh * HD;
    const float* Vg = V + ((size_t)b * S_LEN) * KVDIM + kvh * HD;
    float*       Og = O + ((size_t)(b * S_LEN + qt * 64)) * DIM_ + qh * HD;

    // --- Stage Q (64x64) into Ks region, tf32-converted ---
    #pragma unroll
    for (int h = 0; h < 8; h++) {
        int idx = tid + 128 * h;         // 1024 float4s
        int row = idx >> 4;
        int c4  = (idx & 15) * 4;
        float4 q = *(const float4*)&Qg[(size_t)row * DIM_ + c4];
        *(float4*)&Ks[row * KS_STR + c4] =
            make_float4(tf32f(q.x), tf32f(q.y), tf32f(q.z), tf32f(q.w));
    }
    __syncthreads();

    // --- Load Q fragments into registers (m16 x k64 per warp) ---
    uint32_t qf[8][4];
    {
        const int m0 = warpid * 16;
        #pragma unroll
        for (int ks = 0; ks < 8; ks++) {
            int kb = ks * 8;
            qf[ks][0] = __float_as_uint(Ks[(m0 + g) * KS_STR + kb + t]);
            qf[ks][1] = __float_as_uint(Ks[(m0 + g + 8) * KS_STR + kb + t]);
            qf[ks][2] = __float_as_uint(Ks[(m0 + g) * KS_STR + kb + t + 4]);
            qf[ks][3] = __float_as_uint(Ks[(m0 + g + 8) * KS_STR + kb + t + 4]);
        }
    }
    __syncthreads();

    float m0r = -1e30f, m1r = -1e30f, l0r = 0.0f, l1r = 0.0f;
    float oacc[8][4];
    #pragma unroll
    for (int j = 0; j < 8; j++)
        #pragma unroll
        for (int r = 0; r < 4; r++) oacc[j][r] = 0.0f;

    float* Psw = Ps + warpid * 16 * PS_STR;

    for (int kt = 0; kt < S_LEN / 64; kt++) {
        // --- Stage K,V chunk (64x64 each), tf32-converted ---
        #pragma unroll
        for (int h = 0; h < 8; h++) {
            int idx = tid + 128 * h;
            int row = idx >> 4;
            int c4  = (idx & 15) * 4;
            size_t goff = (size_t)(kt * 64 + row) * KVDIM + c4;
            float4 k4 = *(const float4*)&Kg[goff];
            float4 v4 = *(const float4*)&Vg[goff];
            *(float4*)&Ks[row * KS_STR + c4] =
                make_float4(tf32f(k4.x), tf32f(k4.y), tf32f(k4.z), tf32f(k4.w));
            *(float4*)&Vs[row * VS_STR + c4] =
                make_float4(tf32f(v4.x), tf32f(v4.y), tf32f(v4.z), tf32f(v4.w));
        }
        __syncthreads();

        // --- S = Q @ K^T : m16 x n64, k=64 ---
        float sacc[8][4];
        #pragma unroll
        for (int nt = 0; nt < 8; nt++) {
            #pragma unroll
            for (int r = 0; r < 4; r++) sacc[nt][r] = 0.0f;
            #pragma unroll
            for (int ks = 0; ks < 8; ks++) {
                int kb = ks * 8;
                // B[k=d][n=kv] col-major = K[kv][d]
                uint32_t b0 = __float_as_uint(Ks[(nt * 8 + g) * KS_STR + kb + t]);
                uint32_t b1 = __float_as_uint(Ks[(nt * 8 + g) * KS_STR + kb + t + 4]);
                mma_tf32(sacc[nt], qf[ks][0], qf[ks][1], qf[ks][2], qf[ks][3], b0, b1);
            }
        }

        // --- Online softmax on fragment registers ---
        float mx0 = -1e30f, mx1 = -1e30f;
        #pragma unroll
        for (int nt = 0; nt < 8; nt++) {
            sacc[nt][0] *= sm_scale; sacc[nt][1] *= sm_scale;
            sacc[nt][2] *= sm_scale; sacc[nt][3] *= sm_scale;
            mx0 = fmaxf(mx0, fmaxf(sacc[nt][0], sacc[nt][1]));
            mx1 = fmaxf(mx1, fmaxf(sacc[nt][2], sacc[nt][3]));
        }
        mx0 = fmaxf(mx0, __shfl_xor_sync(0xffffffffu, mx0, 1));
        mx0 = fmaxf(mx0, __shfl_xor_sync(0xffffffffu, mx0, 2));
        mx1 = fmaxf(mx1, __shfl_xor_sync(0xffffffffu, mx1, 1));
        mx1 = fmaxf(mx1, __shfl_xor_sync(0xffffffffu, mx1, 2));

        float mn0 = fmaxf(m0r, mx0), mn1 = fmaxf(m1r, mx1);
        float a0 = __expf(m0r - mn0), a1 = __expf(m1r - mn1);
        m0r = mn0; m1r = mn1;

        float s0 = 0.0f, s1 = 0.0f;
        #pragma unroll
        for (int nt = 0; nt < 8; nt++) {
            float p0 = __expf(sacc[nt][0] - mn0);
            float p1 = __expf(sacc[nt][1] - mn0);
            float p2 = __expf(sacc[nt][2] - mn1);
            float p3 = __expf(sacc[nt][3] - mn1);
            s0 += p0 + p1; s1 += p2 + p3;
            // store P (tf32) to per-warp smem for re-fragmentation
            *(float2*)&Psw[g * PS_STR + nt * 8 + 2 * t] =
                make_float2(tf32f(p0), tf32f(p1));
            *(float2*)&Psw[(g + 8) * PS_STR + nt * 8 + 2 * t] =
                make_float2(tf32f(p2), tf32f(p3));
        }
        s0 += __shfl_xor_sync(0xffffffffu, s0, 1);
        s0 += __shfl_xor_sync(0xffffffffu, s0, 2);
        s1 += __shfl_xor_sync(0xffffffffu, s1, 1);
        s1 += __shfl_xor_sync(0xffffffffu, s1, 2);
        l0r = l0r * a0 + s0;
        l1r = l1r * a1 + s1;

        #pragma unroll
        for (int j = 0; j < 8; j++) {
            oacc[j][0] *= a0; oacc[j][1] *= a0;
            oacc[j][2] *= a1; oacc[j][3] *= a1;
        }
        __syncwarp();

        // --- O += P @ V : m16 x n64, k=64 ---
        #pragma unroll
        for (int kc = 0; kc < 8; kc++) {
            int kb = kc * 8;
            uint32_t pa0 = __float_as_uint(Psw[g * PS_STR + kb + t]);
            uint32_t pa1 = __float_as_uint(Psw[(g + 8) * PS_STR + kb + t]);
            uint32_t pa2 = __float_as_uint(Psw[g * PS_STR + kb + t + 4]);
            uint32_t pa3 = __float_as_uint(Psw[(g + 8) * PS_STR + kb + t + 4]);
            #pragma unroll
            for (int j = 0; j < 8; j++) {
                uint32_t b0 = __float_as_uint(Vs[(kb + t) * VS_STR + j * 8 + g]);
                uint32_t b1 = __float_as_uint(Vs[(kb + t + 4) * VS_STR + j * 8 + g]);
                mma_tf32(oacc[j], pa0, pa1, pa2, pa3, b0, b1);
            }
        }
        __syncthreads();
    }

    // --- Normalize and write out ---
    float inv0 = 1.0f / l0r, inv1 = 1.0f / l1r;
    int qrow0 = warpid * 16 + g;
    #pragma unroll
    for (int j = 0; j < 8; j++) {
        int col = j * 8 + 2 * t;
        *(float2*)&Og[(size_t)qrow0 * DIM_ + col] =
            make_float2(oacc[j][0] * inv0, oacc[j][1] * inv0);
        *(float2*)&Og[(size_t)(qrow0 + 8) * DIM_ + col] =
            make_float2(oacc[j][2] * inv1, oacc[j][3] * inv1);
    }
}

// ---------------------------------------------------------------------------
// Launch
// ---------------------------------------------------------------------------
extern "C" void kernel_launch(void* const* d_in, const int* in_sizes, int n_in,
                              void* d_out, int out_size) {
    (void)in_sizes; (void)n_in; (void)out_size;
    const float* x  = (const float*)d_in[0];
    const float* Wq = (const float*)d_in[1];
    const float* Wk = (const float*)d_in[2];
    const float* Wv = (const float*)d_in[3];
    const float* Wo = (const float*)d_in[4];
    float* out = (float*)d_out;

    float *Qp, *Kp, *Vp, *Op;
    cudaGetSymbolAddress((void**)&Qp, g_Q);
    cudaGetSymbolAddress((void**)&Kp, g_K);
    cudaGetSymbolAddress((void**)&Vp, g_V);
    cudaGetSymbolAddress((void**)&Op, g_O);

    cudaFuncSetAttribute(flash_mma, cudaFuncAttributeMaxDynamicSharedMemorySize,
                         FLASH_SMEM);

    mma_gemm<<<dim3(DIM_ / 128, M_ROWS / 128), 256>>>(x, Wq, Qp, M_ROWS, DIM_, DIM_);
    mma_gemm<<<dim3(KVDIM / 128, M_ROWS / 128), 256>>>(x, Wk, Kp, M_ROWS, KVDIM, DIM_);
    mma_gemm<<<dim3(KVDIM / 128, M_ROWS / 128), 256>>>(x, Wv, Vp, M_ROWS, KVDIM, DIM_);

    flash_mma<<<dim3(S_LEN / 64, NQH, BATCH), 128, FLASH_SMEM>>>(Qp, Kp, Vp, Op);

    mma_gemm<<<dim3(DIM_ / 128, M_ROWS / 128), 256>>>(Op, Wo, out, M_ROWS, DIM_, DIM_);
}

// round 4
// speedup vs baseline: 8.4390x; 2.0222x over previous
#include <cuda_runtime.h>
#include <cuda_fp16.h>
#include <math.h>
#include <stdint.h>

// Problem constants
#define BATCH   2
#define S_LEN   2048
#define DIM_    2048
#define KVDIM   512
#define HD      64
#define NQH     32
#define M_ROWS  (BATCH * S_LEN)   // 4096

// ---------------------------------------------------------------------------
// Scratch (__device__ globals; allocation-free rule)
// ---------------------------------------------------------------------------
__device__ __half g_xh [(size_t)M_ROWS * DIM_];
__device__ __half g_WqT[(size_t)DIM_  * DIM_];   // [N,K] half
__device__ __half g_WkT[(size_t)KVDIM * DIM_];
__device__ __half g_WvT[(size_t)KVDIM * DIM_];
__device__ __half g_WoT[(size_t)DIM_  * DIM_];
__device__ __half g_Qh [(size_t)M_ROWS * DIM_];
__device__ __half g_Kh [(size_t)M_ROWS * KVDIM];
__device__ __half g_Vh [(size_t)M_ROWS * KVDIM];
__device__ __half g_Oh [(size_t)M_ROWS * DIM_];

// ---------------------------------------------------------------------------
// Helpers
// ---------------------------------------------------------------------------
__device__ __forceinline__ uint32_t smem_u32(const void* p) {
    uint32_t a;
    asm("{ .reg .u64 t; cvta.to.shared.u64 t, %1; cvt.u32.u64 %0, t; }"
        : "=r"(a) : "l"(p));
    return a;
}

__device__ __forceinline__ void ldm_x4(uint32_t r[4], uint32_t addr) {
    asm volatile("ldmatrix.sync.aligned.m8n8.x4.shared.b16 {%0,%1,%2,%3}, [%4];"
        : "=r"(r[0]), "=r"(r[1]), "=r"(r[2]), "=r"(r[3]) : "r"(addr));
}

__device__ __forceinline__ void ldm_x4_trans(uint32_t r[4], uint32_t addr) {
    asm volatile("ldmatrix.sync.aligned.m8n8.x4.trans.shared.b16 {%0,%1,%2,%3}, [%4];"
        : "=r"(r[0]), "=r"(r[1]), "=r"(r[2]), "=r"(r[3]) : "r"(addr));
}

__device__ __forceinline__ void mma16816(float c[4], const uint32_t a[4],
                                         uint32_t b0, uint32_t b1) {
    asm volatile(
        "mma.sync.aligned.m16n8k16.row.col.f32.f16.f16.f32 "
        "{%0,%1,%2,%3}, {%4,%5,%6,%7}, {%8,%9}, {%0,%1,%2,%3};"
        : "+f"(c[0]), "+f"(c[1]), "+f"(c[2]), "+f"(c[3])
        : "r"(a[0]), "r"(a[1]), "r"(a[2]), "r"(a[3]), "r"(b0), "r"(b1));
}

__device__ __forceinline__ void cp16(uint32_t dst, const void* src) {
    asm volatile("cp.async.cg.shared.global [%0], [%1], 16;"
        :: "r"(dst), "l"(src));
}
#define CP_COMMIT() asm volatile("cp.async.commit_group;")
#define CP_WAIT1()  asm volatile("cp.async.wait_group 1;")
#define CP_WAIT0()  asm volatile("cp.async.wait_group 0;")

// ---------------------------------------------------------------------------
// Prep: fp32 -> fp16 conversions
// ---------------------------------------------------------------------------
__global__ void f2h_kernel(const float4* __restrict__ in,
                           uint2* __restrict__ out, int n4) {
    for (int i = blockIdx.x * blockDim.x + threadIdx.x; i < n4;
         i += gridDim.x * blockDim.x) {
        float4 v = in[i];
        __half2 h0 = __floats2half2_rn(v.x, v.y);
        __half2 h1 = __floats2half2_rn(v.z, v.w);
        out[i] = make_uint2(*(uint32_t*)&h0, *(uint32_t*)&h1);
    }
}

// W[K,N] fp32 -> WT[N,K] half
__global__ __launch_bounds__(256) void transpose_f2h(
    const float* __restrict__ W, __half* __restrict__ WT, int K, int N)
{
    __shared__ float t[32][33];
    const int n0 = blockIdx.x * 32, k0 = blockIdx.y * 32;
    const int tx = threadIdx.x, ty = threadIdx.y;
    #pragma unroll
    for (int r = 0; r < 4; r++)
        t[ty + r * 8][tx] = W[(size_t)(k0 + ty + r * 8) * N + n0 + tx];
    __syncthreads();
    #pragma unroll
    for (int r = 0; r < 4; r++)
        WT[(size_t)(n0 + ty + r * 8) * K + k0 + tx] =
            __float2half_rn(t[tx][ty + r * 8]);
}

// ---------------------------------------------------------------------------
// fp16 HMMA GEMM: C[M,N] = A[M,K] @ BT[N,K]^T. A,BT half K-major.
// 128x128 block tile, BK=32, 256 threads = 8 warps (2x4), warp tile 64x32.
// 2-stage cp.async double buffer, ldmatrix fragments.
// ---------------------------------------------------------------------------
#define GSTR 40   // smem row stride in halves (80B: ldmatrix conflict-free)

template<bool HALF_OUT>
__global__ __launch_bounds__(256) void hgemm(
    const __half* __restrict__ A, const __half* __restrict__ B,
    void* __restrict__ Cv, int N, int K)
{
    __shared__ __half Ah[2][128 * GSTR];
    __shared__ __half Bh[2][128 * GSTR];

    const int tid  = threadIdx.x;
    const int lane = tid & 31;
    const int wid  = tid >> 5;
    const int wm   = (wid >> 2) * 64;
    const int wn   = (wid & 3) * 32;
    const int bm   = blockIdx.y * 128;
    const int bn   = blockIdx.x * 128;
    const uint32_t aBase = smem_u32(Ah);
    const uint32_t bBase = smem_u32(Bh);

    const int mi = lane >> 3, r8 = lane & 7;
    const int fRowA = (mi & 1) * 8 + r8;   // A-frag m-row offset
    const int fColA = (mi >> 1) * 8;       // A-frag k-col offset
    const int fRowB = (mi >> 1) * 8 + r8;  // B-frag n-row offset
    const int fColB = (mi & 1) * 8;        // B-frag k-col offset

    float acc[4][4][4];
    #pragma unroll
    for (int i = 0; i < 4; i++)
        #pragma unroll
        for (int j = 0; j < 4; j++)
            #pragma unroll
            for (int r = 0; r < 4; r++) acc[i][j][r] = 0.0f;

    auto stage = [&](int s, int k0) {
        #pragma unroll
        for (int h = 0; h < 2; h++) {
            int idx = tid + 256 * h;
            int row = idx >> 2, c8 = (idx & 3) * 8;
            cp16(aBase + (uint32_t)(s * 128 * GSTR + row * GSTR + c8) * 2,
                 A + (size_t)(bm + row) * K + k0 + c8);
            cp16(bBase + (uint32_t)(s * 128 * GSTR + row * GSTR + c8) * 2,
                 B + (size_t)(bn + row) * K + k0 + c8);
        }
        CP_COMMIT();
    };

    const int NIT = K >> 5;
    stage(0, 0);
    for (int i = 0; i < NIT; i++) {
        if (i + 1 < NIT) { stage((i + 1) & 1, (i + 1) << 5); CP_WAIT1(); }
        else             { CP_WAIT0(); }
        __syncthreads();

        const int s = i & 1;
        #pragma unroll
        for (int ks = 0; ks < 2; ks++) {
            uint32_t af[4][4], bf[4][2];
            #pragma unroll
            for (int mt = 0; mt < 4; mt++)
                ldm_x4(af[mt], aBase + (uint32_t)(s * 128 * GSTR +
                    (wm + mt * 16 + fRowA) * GSTR + ks * 16 + fColA) * 2);
            #pragma unroll
            for (int p = 0; p < 2; p++) {
                uint32_t rr[4];
                ldm_x4(rr, bBase + (uint32_t)(s * 128 * GSTR +
                    (wn + p * 16 + fRowB) * GSTR + ks * 16 + fColB) * 2);
                bf[2*p][0] = rr[0]; bf[2*p][1] = rr[1];
                bf[2*p+1][0] = rr[2]; bf[2*p+1][1] = rr[3];
            }
            #pragma unroll
            for (int mt = 0; mt < 4; mt++)
                #pragma unroll
                for (int nt = 0; nt < 4; nt++)
                    mma16816(acc[mt][nt], af[mt], bf[nt][0], bf[nt][1]);
        }
        __syncthreads();
    }

    // Epilogue
    const int g = lane >> 2, t = lane & 3;
    #pragma unroll
    for (int mt = 0; mt < 4; mt++) {
        int row0 = bm + wm + mt * 16 + g;
        #pragma unroll
        for (int nt = 0; nt < 4; nt++) {
            int col = bn + wn + nt * 8 + 2 * t;
            if (HALF_OUT) {
                __half* C = (__half*)Cv;
                *(__half2*)&C[(size_t)row0 * N + col] =
                    __floats2half2_rn(acc[mt][nt][0], acc[mt][nt][1]);
                *(__half2*)&C[(size_t)(row0 + 8) * N + col] =
                    __floats2half2_rn(acc[mt][nt][2], acc[mt][nt][3]);
            } else {
                float* C = (float*)Cv;
                *(float2*)&C[(size_t)row0 * N + col] =
                    make_float2(acc[mt][nt][0], acc[mt][nt][1]);
                *(float2*)&C[(size_t)(row0 + 8) * N + col] =
                    make_float2(acc[mt][nt][2], acc[mt][nt][3]);
            }
        }
    }
}

// ---------------------------------------------------------------------------
// Flash attention, fp16 HMMA, D=64, 64x64 tiles, cp.async double buffer.
// 128 threads = 4 warps; warp w owns q rows [16w,16w+16). Grid (S/64,NQH,B).
// ---------------------------------------------------------------------------
#define KVSTR 72   // smem stride in halves (144B: ldmatrix conflict-free)

__global__ __launch_bounds__(128) void flash_h(
    const __half* __restrict__ Q, const __half* __restrict__ K,
    const __half* __restrict__ V, __half* __restrict__ O)
{
    __shared__ __half Ks[2][64 * KVSTR];
    __shared__ __half Vs[2][64 * KVSTR];
    __shared__ __half Ps[4][16 * KVSTR];

    const int tid  = threadIdx.x;
    const int lane = tid & 31;
    const int wid  = tid >> 5;
    const int g    = lane >> 2;
    const int t    = lane & 3;
    const int qt   = blockIdx.x;
    const int qh   = blockIdx.y;
    const int b    = blockIdx.z;
    const int kvh  = qh >> 2;
    const float sm_scale = 0.125f;

    const __half* Qg = Q + ((size_t)(b * S_LEN + qt * 64)) * DIM_ + qh * HD;
    const __half* Kg = K + ((size_t)b * S_LEN) * KVDIM + kvh * HD;
    const __half* Vg = V + ((size_t)b * S_LEN) * KVDIM + kvh * HD;
    __half*       Og = O + ((size_t)(b * S_LEN + qt * 64)) * DIM_ + qh * HD;

    const uint32_t ksBase = smem_u32(Ks);
    const uint32_t vsBase = smem_u32(Vs);
    const uint32_t psBase = smem_u32(Ps) + (uint32_t)(wid * 16 * KVSTR) * 2;
    __half* PsPtr = &Ps[wid][0];

    const int mi = lane >> 3, r8 = lane & 7;
    const int aRow = (mi & 1) * 8 + r8;   // A-frag row off (also V-trans seq off)
    const int aCol = (mi >> 1) * 8;       // A-frag col off (also V-trans d off)
    const int bRow = (mi >> 1) * 8 + r8;  // B-frag (K) n-row off
    const int bCol = (mi & 1) * 8;        // B-frag (K) k-col off

    // --- Stage Q into Ks[0], load Q fragments ---
    #pragma unroll
    for (int h = 0; h < 4; h++) {
        int idx = tid + 128 * h;
        int row = idx >> 3, c8 = (idx & 7) * 8;
        *(uint4*)&Ks[0][row * KVSTR + c8] =
            *(const uint4*)&Qg[(size_t)row * DIM_ + c8];
    }
    __syncthreads();

    uint32_t qf[4][4];
    {
        const int m0 = wid * 16;
        #pragma unroll
        for (int ks = 0; ks < 4; ks++)
            ldm_x4(qf[ks], ksBase + (uint32_t)((m0 + aRow) * KVSTR +
                                               ks * 16 + aCol) * 2);
    }
    __syncthreads();

    auto stage = [&](int s, int kt) {
        const __half* kg = Kg + (size_t)(kt * 64) * KVDIM;
        const __half* vg = Vg + (size_t)(kt * 64) * KVDIM;
        #pragma unroll
        for (int h = 0; h < 4; h++) {
            int idx = tid + 128 * h;
            int row = idx >> 3, c8 = (idx & 7) * 8;
            uint32_t so = (uint32_t)(s * 64 * KVSTR + row * KVSTR + c8) * 2;
            cp16(ksBase + so, kg + (size_t)row * KVDIM + c8);
            cp16(vsBase + so, vg + (size_t)row * KVDIM + c8);
        }
        CP_COMMIT();
    };

    float m0r = -1e30f, m1r = -1e30f, l0r = 0.0f, l1r = 0.0f;
    float oacc[8][4];
    #pragma unroll
    for (int j = 0; j < 8; j++)
        #pragma unroll
        for (int r = 0; r < 4; r++) oacc[j][r] = 0.0f;

    const int NC = S_LEN / 64;
    stage(0, 0);
    for (int kt = 0; kt < NC; kt++) {
        if (kt + 1 < NC) { stage((kt + 1) & 1, kt + 1); CP_WAIT1(); }
        else             { CP_WAIT0(); }
        __syncthreads();

        const int s = kt & 1;
        const uint32_t ksB = ksBase + (uint32_t)(s * 64 * KVSTR) * 2;
        const uint32_t vsB = vsBase + (uint32_t)(s * 64 * KVSTR) * 2;

        // --- S = Q @ K^T ---
        float sacc[8][4];
        #pragma unroll
        for (int nt = 0; nt < 8; nt++)
            #pragma unroll
            for (int r = 0; r < 4; r++) sacc[nt][r] = 0.0f;

        #pragma unroll
        for (int ks = 0; ks < 4; ks++) {
            #pragma unroll
            for (int p = 0; p < 4; p++) {
                uint32_t rr[4];
                ldm_x4(rr, ksB + (uint32_t)((p * 16 + bRow) * KVSTR +
                                            ks * 16 + bCol) * 2);
                mma16816(sacc[2*p],   qf[ks], rr[0], rr[1]);
                mma16816(sacc[2*p+1], qf[ks], rr[2], rr[3]);
            }
        }

        // --- Online softmax ---
        float mx0 = -1e30f, mx1 = -1e30f;
        #pragma unroll
        for (int nt = 0; nt < 8; nt++) {
            sacc[nt][0] *= sm_scale; sacc[nt][1] *= sm_scale;
            sacc[nt][2] *= sm_scale; sacc[nt][3] *= sm_scale;
            mx0 = fmaxf(mx0, fmaxf(sacc[nt][0], sacc[nt][1]));
            mx1 = fmaxf(mx1, fmaxf(sacc[nt][2], sacc[nt][3]));
        }
        mx0 = fmaxf(mx0, __shfl_xor_sync(0xffffffffu, mx0, 1));
        mx0 = fmaxf(mx0, __shfl_xor_sync(0xffffffffu, mx0, 2));
        mx1 = fmaxf(mx1, __shfl_xor_sync(0xffffffffu, mx1, 1));
        mx1 = fmaxf(mx1, __shfl_xor_sync(0xffffffffu, mx1, 2));

        float mn0 = fmaxf(m0r, mx0), mn1 = fmaxf(m1r, mx1);
        float a0 = __expf(m0r - mn0), a1 = __expf(m1r - mn1);
        m0r = mn0; m1r = mn1;

        float s0 = 0.0f, s1 = 0.0f;
        #pragma unroll
        for (int nt = 0; nt < 8; nt++) {
            float p0 = __expf(sacc[nt][0] - mn0);
            float p1 = __expf(sacc[nt][1] - mn0);
            float p2 = __expf(sacc[nt][2] - mn1);
            float p3 = __expf(sacc[nt][3] - mn1);
            s0 += p0 + p1; s1 += p2 + p3;
            *(__half2*)&PsPtr[g * KVSTR + nt * 8 + 2 * t] =
                __floats2half2_rn(p0, p1);
            *(__half2*)&PsPtr[(g + 8) * KVSTR + nt * 8 + 2 * t] =
                __floats2half2_rn(p2, p3);
        }
        s0 += __shfl_xor_sync(0xffffffffu, s0, 1);
        s0 += __shfl_xor_sync(0xffffffffu, s0, 2);
        s1 += __shfl_xor_sync(0xffffffffu, s1, 1);
        s1 += __shfl_xor_sync(0xffffffffu, s1, 2);
        l0r = l0r * a0 + s0;
        l1r = l1r * a1 + s1;

        #pragma unroll
        for (int j = 0; j < 8; j++) {
            oacc[j][0] *= a0; oacc[j][1] *= a0;
            oacc[j][2] *= a1; oacc[j][3] *= a1;
        }
        __syncwarp();

        // --- O += P @ V ---
        #pragma unroll
        for (int ks = 0; ks < 4; ks++) {
            uint32_t pf[4];
            ldm_x4(pf, psBase + (uint32_t)(aRow * KVSTR + ks * 16 + aCol) * 2);
            #pragma unroll
            for (int p = 0; p < 4; p++) {
                uint32_t rr[4];
                ldm_x4_trans(rr, vsB + (uint32_t)((ks * 16 + aRow) * KVSTR +
                                                  p * 16 + aCol) * 2);
                mma16816(oacc[2*p],   pf, rr[0], rr[1]);
                mma16816(oacc[2*p+1], pf, rr[2], rr[3]);
            }
        }
        __syncthreads();
    }

    // --- Normalize and write out (half) ---
    float inv0 = 1.0f / l0r, inv1 = 1.0f / l1r;
    int qrow0 = wid * 16 + g;
    #pragma unroll
    for (int j = 0; j < 8; j++) {
        int col = j * 8 + 2 * t;
        *(__half2*)&Og[(size_t)qrow0 * DIM_ + col] =
            __floats2half2_rn(oacc[j][0] * inv0, oacc[j][1] * inv0);
        *(__half2*)&Og[(size_t)(qrow0 + 8) * DIM_ + col] =
            __floats2half2_rn(oacc[j][2] * inv1, oacc[j][3] * inv1);
    }
}

// ---------------------------------------------------------------------------
// Launch
// ---------------------------------------------------------------------------
extern "C" void kernel_launch(void* const* d_in, const int* in_sizes, int n_in,
                              void* d_out, int out_size) {
    (void)in_sizes; (void)n_in; (void)out_size;
    const float* x  = (const float*)d_in[0];
    const float* Wq = (const float*)d_in[1];
    const float* Wk = (const float*)d_in[2];
    const float* Wv = (const float*)d_in[3];
    const float* Wo = (const float*)d_in[4];
    float* out = (float*)d_out;

    __half *xh, *WqT, *WkT, *WvT, *WoT, *Qh, *Kh, *Vh, *Oh;
    cudaGetSymbolAddress((void**)&xh,  g_xh);
    cudaGetSymbolAddress((void**)&WqT, g_WqT);
    cudaGetSymbolAddress((void**)&WkT, g_WkT);
    cudaGetSymbolAddress((void**)&WvT, g_WvT);
    cudaGetSymbolAddress((void**)&WoT, g_WoT);
    cudaGetSymbolAddress((void**)&Qh,  g_Qh);
    cudaGetSymbolAddress((void**)&Kh,  g_Kh);
    cudaGetSymbolAddress((void**)&Vh,  g_Vh);
    cudaGetSymbolAddress((void**)&Oh,  g_Oh);

    dim3 tb(32, 8);
    // Prep: convert x; transpose+convert weights
    f2h_kernel<<<1024, 256>>>((const float4*)x, (uint2*)xh,
                              (M_ROWS * DIM_) / 4);
    transpose_f2h<<<dim3(DIM_ / 32,  DIM_ / 32), tb>>>(Wq, WqT, DIM_, DIM_);
    transpose_f2h<<<dim3(KVDIM / 32, DIM_ / 32), tb>>>(Wk, WkT, DIM_, KVDIM);
    transpose_f2h<<<dim3(KVDIM / 32, DIM_ / 32), tb>>>(Wv, WvT, DIM_, KVDIM);
    transpose_f2h<<<dim3(DIM_ / 32,  DIM_ / 32), tb>>>(Wo, WoT, DIM_, DIM_);

    // Projections
    hgemm<true><<<dim3(DIM_ / 128,  M_ROWS / 128), 256>>>(xh, WqT, Qh, DIM_,  DIM_);
    hgemm<true><<<dim3(KVDIM / 128, M_ROWS / 128), 256>>>(xh, WkT, Kh, KVDIM, DIM_);
    hgemm<true><<<dim3(KVDIM / 128, M_ROWS / 128), 256>>>(xh, WvT, Vh, KVDIM, DIM_);

    // Attention
    flash_h<<<dim3(S_LEN / 64, NQH, BATCH), 128>>>(Qh, Kh, Vh, Oh);

    // Output projection (fp32 out)
    hgemm<false><<<dim3(DIM_ / 128, M_ROWS / 128), 256>>>(Oh, WoT, out, DIM_, DIM_);
}

// round 5
// speedup vs baseline: 8.4941x; 1.0065x over previous
#include <cuda_runtime.h>
#include <cuda_fp16.h>
#include <math.h>
#include <stdint.h>

// Problem constants
#define BATCH   2
#define S_LEN   2048
#define DIM_    2048
#define KVDIM   512
#define QKVN    3072          // fused projection output width (2048+512+512)
#define HD      64
#define NQH     32
#define M_ROWS  (BATCH * S_LEN)   // 4096

// ---------------------------------------------------------------------------
// Scratch (__device__ globals; allocation-free rule)
// ---------------------------------------------------------------------------
__device__ __half g_xh  [(size_t)M_ROWS * DIM_];     //  16 MB
__device__ __half g_Wqkv[(size_t)QKVN * DIM_];       //  12 MB  [N=3072,K] half
__device__ __half g_WoT [(size_t)DIM_ * DIM_];       //   8 MB
__device__ __half g_QKV [(size_t)M_ROWS * QKVN];     //  24 MB
__device__ __half g_Oh  [(size_t)M_ROWS * DIM_];     //  16 MB

// ---------------------------------------------------------------------------
// Helpers
// ---------------------------------------------------------------------------
__device__ __forceinline__ uint32_t smem_u32(const void* p) {
    uint32_t a;
    asm("{ .reg .u64 t; cvta.to.shared.u64 t, %1; cvt.u32.u64 %0, t; }"
        : "=r"(a) : "l"(p));
    return a;
}

__device__ __forceinline__ void ldm_x4(uint32_t r[4], uint32_t addr) {
    asm volatile("ldmatrix.sync.aligned.m8n8.x4.shared.b16 {%0,%1,%2,%3}, [%4];"
        : "=r"(r[0]), "=r"(r[1]), "=r"(r[2]), "=r"(r[3]) : "r"(addr));
}

__device__ __forceinline__ void ldm_x4_trans(uint32_t r[4], uint32_t addr) {
    asm volatile("ldmatrix.sync.aligned.m8n8.x4.trans.shared.b16 {%0,%1,%2,%3}, [%4];"
        : "=r"(r[0]), "=r"(r[1]), "=r"(r[2]), "=r"(r[3]) : "r"(addr));
}

__device__ __forceinline__ void mma16816(float c[4], const uint32_t a[4],
                                         uint32_t b0, uint32_t b1) {
    asm volatile(
        "mma.sync.aligned.m16n8k16.row.col.f32.f16.f16.f32 "
        "{%0,%1,%2,%3}, {%4,%5,%6,%7}, {%8,%9}, {%0,%1,%2,%3};"
        : "+f"(c[0]), "+f"(c[1]), "+f"(c[2]), "+f"(c[3])
        : "r"(a[0]), "r"(a[1]), "r"(a[2]), "r"(a[3]), "r"(b0), "r"(b1));
}

__device__ __forceinline__ void cp16(uint32_t dst, const void* src) {
    asm volatile("cp.async.cg.shared.global [%0], [%1], 16;"
        :: "r"(dst), "l"(src));
}
#define CP_COMMIT() asm volatile("cp.async.commit_group;")
#define CP_WAIT1()  asm volatile("cp.async.wait_group 1;")
#define CP_WAIT0()  asm volatile("cp.async.wait_group 0;")

// ---------------------------------------------------------------------------
// Prep: fp32 -> fp16 conversions
// ---------------------------------------------------------------------------
__global__ void f2h_kernel(const float4* __restrict__ in,
                           uint2* __restrict__ out, int n4) {
    for (int i = blockIdx.x * blockDim.x + threadIdx.x; i < n4;
         i += gridDim.x * blockDim.x) {
        float4 v = in[i];
        __half2 h0 = __floats2half2_rn(v.x, v.y);
        __half2 h1 = __floats2half2_rn(v.z, v.w);
        out[i] = make_uint2(*(uint32_t*)&h0, *(uint32_t*)&h1);
    }
}

// W[K,N] fp32 -> WT[N,K] half
__global__ __launch_bounds__(256) void transpose_f2h(
    const float* __restrict__ W, __half* __restrict__ WT, int K, int N)
{
    __shared__ float t[32][33];
    const int n0 = blockIdx.x * 32, k0 = blockIdx.y * 32;
    const int tx = threadIdx.x, ty = threadIdx.y;
    #pragma unroll
    for (int r = 0; r < 4; r++)
        t[ty + r * 8][tx] = W[(size_t)(k0 + ty + r * 8) * N + n0 + tx];
    __syncthreads();
    #pragma unroll
    for (int r = 0; r < 4; r++)
        WT[(size_t)(n0 + ty + r * 8) * K + k0 + tx] =
            __float2half_rn(t[tx][ty + r * 8]);
}

// ---------------------------------------------------------------------------
// fp16 HMMA GEMM: C[M,N] = A[M,K] @ BT[N,K]^T. A,BT half K-major.
// 128x128 block tile, BK=32, 256 threads = 8 warps (2x4), warp tile 64x32.
// ---------------------------------------------------------------------------
#define GSTR 40   // smem row stride in halves (80B: ldmatrix conflict-free)

template<bool HALF_OUT>
__global__ __launch_bounds__(256) void hgemm(
    const __half* __restrict__ A, const __half* __restrict__ B,
    void* __restrict__ Cv, int N, int K)
{
    __shared__ __half Ah[2][128 * GSTR];
    __shared__ __half Bh[2][128 * GSTR];

    const int tid  = threadIdx.x;
    const int lane = tid & 31;
    const int wid  = tid >> 5;
    const int wm   = (wid >> 2) * 64;
    const int wn   = (wid & 3) * 32;
    const int bm   = blockIdx.y * 128;
    const int bn   = blockIdx.x * 128;
    const uint32_t aBase = smem_u32(Ah);
    const uint32_t bBase = smem_u32(Bh);

    const int mi = lane >> 3, r8 = lane & 7;
    const int fRowA = (mi & 1) * 8 + r8;
    const int fColA = (mi >> 1) * 8;
    const int fRowB = (mi >> 1) * 8 + r8;
    const int fColB = (mi & 1) * 8;

    float acc[4][4][4];
    #pragma unroll
    for (int i = 0; i < 4; i++)
        #pragma unroll
        for (int j = 0; j < 4; j++)
            #pragma unroll
            for (int r = 0; r < 4; r++) acc[i][j][r] = 0.0f;

    auto stage = [&](int s, int k0) {
        #pragma unroll
        for (int h = 0; h < 2; h++) {
            int idx = tid + 256 * h;
            int row = idx >> 2, c8 = (idx & 3) * 8;
            cp16(aBase + (uint32_t)(s * 128 * GSTR + row * GSTR + c8) * 2,
                 A + (size_t)(bm + row) * K + k0 + c8);
            cp16(bBase + (uint32_t)(s * 128 * GSTR + row * GSTR + c8) * 2,
                 B + (size_t)(bn + row) * K + k0 + c8);
        }
        CP_COMMIT();
    };

    const int NIT = K >> 5;
    stage(0, 0);
    for (int i = 0; i < NIT; i++) {
        if (i + 1 < NIT) { stage((i + 1) & 1, (i + 1) << 5); CP_WAIT1(); }
        else             { CP_WAIT0(); }
        __syncthreads();

        const int s = i & 1;
        #pragma unroll
        for (int ks = 0; ks < 2; ks++) {
            uint32_t af[4][4], bf[4][2];
            #pragma unroll
            for (int mt = 0; mt < 4; mt++)
                ldm_x4(af[mt], aBase + (uint32_t)(s * 128 * GSTR +
                    (wm + mt * 16 + fRowA) * GSTR + ks * 16 + fColA) * 2);
            #pragma unroll
            for (int p = 0; p < 2; p++) {
                uint32_t rr[4];
                ldm_x4(rr, bBase + (uint32_t)(s * 128 * GSTR +
                    (wn + p * 16 + fRowB) * GSTR + ks * 16 + fColB) * 2);
                bf[2*p][0] = rr[0]; bf[2*p][1] = rr[1];
                bf[2*p+1][0] = rr[2]; bf[2*p+1][1] = rr[3];
            }
            #pragma unroll
            for (int mt = 0; mt < 4; mt++)
                #pragma unroll
                for (int nt = 0; nt < 4; nt++)
                    mma16816(acc[mt][nt], af[mt], bf[nt][0], bf[nt][1]);
        }
        __syncthreads();
    }

    const int g = lane >> 2, t = lane & 3;
    #pragma unroll
    for (int mt = 0; mt < 4; mt++) {
        int row0 = bm + wm + mt * 16 + g;
        #pragma unroll
        for (int nt = 0; nt < 4; nt++) {
            int col = bn + wn + nt * 8 + 2 * t;
            if (HALF_OUT) {
                __half* C = (__half*)Cv;
                *(__half2*)&C[(size_t)row0 * N + col] =
                    __floats2half2_rn(acc[mt][nt][0], acc[mt][nt][1]);
                *(__half2*)&C[(size_t)(row0 + 8) * N + col] =
                    __floats2half2_rn(acc[mt][nt][2], acc[mt][nt][3]);
            } else {
                float* C = (float*)Cv;
                *(float2*)&C[(size_t)row0 * N + col] =
                    make_float2(acc[mt][nt][0], acc[mt][nt][1]);
                *(float2*)&C[(size_t)(row0 + 8) * N + col] =
                    make_float2(acc[mt][nt][2], acc[mt][nt][3]);
            }
        }
    }
}

// ---------------------------------------------------------------------------
// Flash attention, fp16 HMMA, GQA-fused: 2 q-heads share the K/V stream.
// 256 threads = 8 warps; warp w: head (w>>2) of the pair, rows (w&3)*16.
// Q/K/V read from fused QKV buffer (row stride 3072).
// Grid: (S/64, N_KV*2, BATCH); blockIdx.y = kvh*2 + head_pair.
// ---------------------------------------------------------------------------
#define KVSTR 72                 // smem stride in halves
#define KVH_STAGE 9216           // K+V halves per stage (2 * 64*72)
#define OFF_K(s) ((unsigned)(s) * KVH_STAGE)
#define OFF_V(s) ((unsigned)(s) * KVH_STAGE + 4608)
#define OFF_P    18432
#define FLASH_HALVES (OFF_P + 8 * 16 * KVSTR)   // 27648
#define FLASH_SMEM   (FLASH_HALVES * 2)          // 55296 B

__global__ __launch_bounds__(256) void flash_h2(
    const __half* __restrict__ QKV, __half* __restrict__ O)
{
    extern __shared__ __half sm[];
    const uint32_t smBase = smem_u32(sm);

    const int tid  = threadIdx.x;
    const int lane = tid & 31;
    const int wid  = tid >> 5;
    const int g    = lane >> 2;
    const int t    = lane & 3;
    const int qt   = blockIdx.x;
    const int kvh  = blockIdx.y >> 1;
    const int hp   = blockIdx.y & 1;
    const int b    = blockIdx.z;
    const int h2   = wid >> 2;            // head within pair (0/1)
    const int wq   = (wid & 3) * 16;      // warp's q-row offset in 64-row tile
    const int qh   = kvh * 4 + hp * 2 + h2;
    const float sm_scale = 0.125f;

    const __half* Qbase = QKV + ((size_t)(b * S_LEN + qt * 64)) * QKVN;
    const __half* Kbase = QKV + ((size_t)b * S_LEN) * QKVN + 2048 + kvh * HD;
    const __half* Vbase = QKV + ((size_t)b * S_LEN) * QKVN + 2560 + kvh * HD;
    __half*       Og    = O + ((size_t)(b * S_LEN + qt * 64 + wq)) * DIM_ + qh * HD;

    const int mi = lane >> 3, r8 = lane & 7;
    const int aRow = (mi & 1) * 8 + r8;
    const int aCol = (mi >> 1) * 8;
    const int bRow = (mi >> 1) * 8 + r8;
    const int bCol = (mi & 1) * 8;

    // --- Stage both heads' Q (128 rows x 64) into KV region, grab fragments ---
    #pragma unroll
    for (int h = 0; h < 4; h++) {
        int idx = tid + 256 * h;          // 0..1023 uint4
        int row = idx >> 3, c8 = (idx & 7) * 8;
        int hh = row >> 6, r = row & 63;
        *(uint4*)&sm[row * KVSTR + c8] =
            *(const uint4*)&Qbase[(size_t)r * QKVN + (kvh * 4 + hp * 2 + hh) * HD + c8];
    }
    __syncthreads();

    uint32_t qf[4][4];
    {
        const int m0 = h2 * 64 + wq;
        #pragma unroll
        for (int ks = 0; ks < 4; ks++)
            ldm_x4(qf[ks], smBase + (uint32_t)((m0 + aRow) * KVSTR +
                                               ks * 16 + aCol) * 2);
    }
    __syncthreads();

    auto stage = [&](int s, int kt) {
        const __half* kg = Kbase + (size_t)(kt * 64) * QKVN;
        const __half* vg = Vbase + (size_t)(kt * 64) * QKVN;
        #pragma unroll
        for (int h = 0; h < 2; h++) {
            int idx = tid + 256 * h;      // 0..511
            int row = idx >> 3, c8 = (idx & 7) * 8;
            cp16(smBase + (OFF_K(s) + row * KVSTR + c8) * 2,
                 kg + (size_t)row * QKVN + c8);
            cp16(smBase + (OFF_V(s) + row * KVSTR + c8) * 2,
                 vg + (size_t)row * QKVN + c8);
        }
        CP_COMMIT();
    };

    const uint32_t psBase = smBase + (OFF_P + (unsigned)wid * 16 * KVSTR) * 2;
    __half* PsPtr = &sm[OFF_P + wid * 16 * KVSTR];

    float m0r = -1e30f, m1r = -1e30f, l0r = 0.0f, l1r = 0.0f;
    float oacc[8][4];
    #pragma unroll
    for (int j = 0; j < 8; j++)
        #pragma unroll
        for (int r = 0; r < 4; r++) oacc[j][r] = 0.0f;

    const int NC = S_LEN / 64;
    stage(0, 0);
    for (int kt = 0; kt < NC; kt++) {
        if (kt + 1 < NC) { stage((kt + 1) & 1, kt + 1); CP_WAIT1(); }
        else             { CP_WAIT0(); }
        __syncthreads();

        const int s = kt & 1;
        const uint32_t ksB = smBase + OFF_K(s) * 2;
        const uint32_t vsB = smBase + OFF_V(s) * 2;

        // --- S = Q @ K^T ---
        float sacc[8][4];
        #pragma unroll
        for (int nt = 0; nt < 8; nt++)
            #pragma unroll
            for (int r = 0; r < 4; r++) sacc[nt][r] = 0.0f;

        #pragma unroll
        for (int ks = 0; ks < 4; ks++) {
            #pragma unroll
            for (int p = 0; p < 4; p++) {
                uint32_t rr[4];
                ldm_x4(rr, ksB + (uint32_t)((p * 16 + bRow) * KVSTR +
                                            ks * 16 + bCol) * 2);
                mma16816(sacc[2*p],   qf[ks], rr[0], rr[1]);
                mma16816(sacc[2*p+1], qf[ks], rr[2], rr[3]);
            }
        }

        // --- Online softmax ---
        float mx0 = -1e30f, mx1 = -1e30f;
        #pragma unroll
        for (int nt = 0; nt < 8; nt++) {
            sacc[nt][0] *= sm_scale; sacc[nt][1] *= sm_scale;
            sacc[nt][2] *= sm_scale; sacc[nt][3] *= sm_scale;
            mx0 = fmaxf(mx0, fmaxf(sacc[nt][0], sacc[nt][1]));
            mx1 = fmaxf(mx1, fmaxf(sacc[nt][2], sacc[nt][3]));
        }
        mx0 = fmaxf(mx0, __shfl_xor_sync(0xffffffffu, mx0, 1));
        mx0 = fmaxf(mx0, __shfl_xor_sync(0xffffffffu, mx0, 2));
        mx1 = fmaxf(mx1, __shfl_xor_sync(0xffffffffu, mx1, 1));
        mx1 = fmaxf(mx1, __shfl_xor_sync(0xffffffffu, mx1, 2));

        float mn0 = fmaxf(m0r, mx0), mn1 = fmaxf(m1r, mx1);
        float a0 = __expf(m0r - mn0), a1 = __expf(m1r - mn1);
        m0r = mn0; m1r = mn1;

        float s0 = 0.0f, s1 = 0.0f;
        #pragma unroll
        for (int nt = 0; nt < 8; nt++) {
            float p0 = __expf(sacc[nt][0] - mn0);
            float p1 = __expf(sacc[nt][1] - mn0);
            float p2 = __expf(sacc[nt][2] - mn1);
            float p3 = __expf(sacc[nt][3] - mn1);
            s0 += p0 + p1; s1 += p2 + p3;
            *(__half2*)&PsPtr[g * KVSTR + nt * 8 + 2 * t] =
                __floats2half2_rn(p0, p1);
            *(__half2*)&PsPtr[(g + 8) * KVSTR + nt * 8 + 2 * t] =
                __floats2half2_rn(p2, p3);
        }
        s0 += __shfl_xor_sync(0xffffffffu, s0, 1);
        s0 += __shfl_xor_sync(0xffffffffu, s0, 2);
        s1 += __shfl_xor_sync(0xffffffffu, s1, 1);
        s1 += __shfl_xor_sync(0xffffffffu, s1, 2);
        l0r = l0r * a0 + s0;
        l1r = l1r * a1 + s1;

        #pragma unroll
        for (int j = 0; j < 8; j++) {
            oacc[j][0] *= a0; oacc[j][1] *= a0;
            oacc[j][2] *= a1; oacc[j][3] *= a1;
        }
        __syncwarp();

        // --- O += P @ V ---
        #pragma unroll
        for (int ks = 0; ks < 4; ks++) {
            uint32_t pf[4];
            ldm_x4(pf, psBase + (uint32_t)(aRow * KVSTR + ks * 16 + aCol) * 2);
            #pragma unroll
            for (int p = 0; p < 4; p++) {
                uint32_t rr[4];
                ldm_x4_trans(rr, vsB + (uint32_t)((ks * 16 + aRow) * KVSTR +
                                                  p * 16 + aCol) * 2);
                mma16816(oacc[2*p],   pf, rr[0], rr[1]);
                mma16816(oacc[2*p+1], pf, rr[2], rr[3]);
            }
        }
        __syncthreads();
    }

    // --- Normalize and write out (half) ---
    float inv0 = 1.0f / l0r, inv1 = 1.0f / l1r;
    #pragma unroll
    for (int j = 0; j < 8; j++) {
        int col = j * 8 + 2 * t;
        *(__half2*)&Og[(size_t)g * DIM_ + col] =
            __floats2half2_rn(oacc[j][0] * inv0, oacc[j][1] * inv0);
        *(__half2*)&Og[(size_t)(g + 8) * DIM_ + col] =
            __floats2half2_rn(oacc[j][2] * inv1, oacc[j][3] * inv1);
    }
}

// ---------------------------------------------------------------------------
// Launch
// ---------------------------------------------------------------------------
extern "C" void kernel_launch(void* const* d_in, const int* in_sizes, int n_in,
                              void* d_out, int out_size) {
    (void)in_sizes; (void)n_in; (void)out_size;
    const float* x  = (const float*)d_in[0];
    const float* Wq = (const float*)d_in[1];
    const float* Wk = (const float*)d_in[2];
    const float* Wv = (const float*)d_in[3];
    const float* Wo = (const float*)d_in[4];
    float* out = (float*)d_out;

    __half *xh, *Wqkv, *WoT, *QKVh, *Oh;
    cudaGetSymbolAddress((void**)&xh,   g_xh);
    cudaGetSymbolAddress((void**)&Wqkv, g_Wqkv);
    cudaGetSymbolAddress((void**)&WoT,  g_WoT);
    cudaGetSymbolAddress((void**)&QKVh, g_QKV);
    cudaGetSymbolAddress((void**)&Oh,   g_Oh);

    cudaFuncSetAttribute(flash_h2, cudaFuncAttributeMaxDynamicSharedMemorySize,
                         FLASH_SMEM);

    dim3 tb(32, 8);
    // Prep: convert x; transpose+convert weights into fused layout
    f2h_kernel<<<1024, 256>>>((const float4*)x, (uint2*)xh,
                              (M_ROWS * DIM_) / 4);
    transpose_f2h<<<dim3(DIM_ / 32,  DIM_ / 32), tb>>>(Wq, Wqkv, DIM_, DIM_);
    transpose_f2h<<<dim3(KVDIM / 32, DIM_ / 32), tb>>>(
        Wk, Wqkv + (size_t)2048 * DIM_, DIM_, KVDIM);
    transpose_f2h<<<dim3(KVDIM / 32, DIM_ / 32), tb>>>(
        Wv, Wqkv + (size_t)2560 * DIM_, DIM_, KVDIM);
    transpose_f2h<<<dim3(DIM_ / 32,  DIM_ / 32), tb>>>(Wo, WoT, DIM_, DIM_);

    // Fused QKV projection: [4096,2048] @ [3072,2048]^T -> [4096,3072]
    hgemm<true><<<dim3(QKVN / 128, M_ROWS / 128), 256>>>(xh, Wqkv, QKVh,
                                                         QKVN, DIM_);

    // GQA-fused attention: 2 heads per CTA
    flash_h2<<<dim3(S_LEN / 64, 16, BATCH), 256, FLASH_SMEM>>>(QKVh, Oh);

    // Output projection (fp32 out)
    hgemm<false><<<dim3(DIM_ / 128, M_ROWS / 128), 256>>>(Oh, WoT, out,
                                                          DIM_, DIM_);
}

// round 6
// speedup vs baseline: 10.3499x; 1.2185x over previous
#include <cuda_runtime.h>
#include <cuda_fp16.h>
#include <math.h>
#include <stdint.h>

// Problem constants
#define BATCH   2
#define S_LEN   2048
#define DIM_    2048
#define KVDIM   512
#define QKVN    3072
#define HD      64
#define NQH     32
#define M_ROWS  (BATCH * S_LEN)   // 4096

// ---------------------------------------------------------------------------
// Scratch
// ---------------------------------------------------------------------------
__device__ __half g_xh  [(size_t)M_ROWS * DIM_];
__device__ __half g_Wqkv[(size_t)QKVN * DIM_];   // [N,K] half
__device__ __half g_WoT [(size_t)DIM_ * DIM_];
__device__ __half g_QKV [(size_t)M_ROWS * QKVN];
__device__ __half g_Oh  [(size_t)M_ROWS * DIM_];

// ---------------------------------------------------------------------------
// Helpers
// ---------------------------------------------------------------------------
__device__ __forceinline__ uint32_t smem_u32(const void* p) {
    uint32_t a;
    asm("{ .reg .u64 t; cvta.to.shared.u64 t, %1; cvt.u32.u64 %0, t; }"
        : "=r"(a) : "l"(p));
    return a;
}

__device__ __forceinline__ void ldm_x4(uint32_t r[4], uint32_t addr) {
    asm volatile("ldmatrix.sync.aligned.m8n8.x4.shared.b16 {%0,%1,%2,%3}, [%4];"
        : "=r"(r[0]), "=r"(r[1]), "=r"(r[2]), "=r"(r[3]) : "r"(addr));
}

__device__ __forceinline__ void ldm_x4_trans(uint32_t r[4], uint32_t addr) {
    asm volatile("ldmatrix.sync.aligned.m8n8.x4.trans.shared.b16 {%0,%1,%2,%3}, [%4];"
        : "=r"(r[0]), "=r"(r[1]), "=r"(r[2]), "=r"(r[3]) : "r"(addr));
}

__device__ __forceinline__ void mma16816(float c[4], const uint32_t a[4],
                                         uint32_t b0, uint32_t b1) {
    asm volatile(
        "mma.sync.aligned.m16n8k16.row.col.f32.f16.f16.f32 "
        "{%0,%1,%2,%3}, {%4,%5,%6,%7}, {%8,%9}, {%0,%1,%2,%3};"
        : "+f"(c[0]), "+f"(c[1]), "+f"(c[2]), "+f"(c[3])
        : "r"(a[0]), "r"(a[1]), "r"(a[2]), "r"(a[3]), "r"(b0), "r"(b1));
}

__device__ __forceinline__ void cp16(uint32_t dst, const void* src) {
    asm volatile("cp.async.cg.shared.global [%0], [%1], 16;"
        :: "r"(dst), "l"(src));
}
#define CP_COMMIT() asm volatile("cp.async.commit_group;")
#define CP_WAIT0()  asm volatile("cp.async.wait_group 0;")
#define CP_WAIT1()  asm volatile("cp.async.wait_group 1;")
#define CP_WAIT2()  asm volatile("cp.async.wait_group 2;")
#define CP_WAIT3()  asm volatile("cp.async.wait_group 3;")

__device__ __forceinline__ uint32_t h2u(float a, float b) {
    __half2 h = __floats2half2_rn(a, b);
    return *(uint32_t*)&h;
}

// ---------------------------------------------------------------------------
// Prep kernels
// ---------------------------------------------------------------------------
__global__ void f2h_kernel(const float4* __restrict__ in,
                           uint2* __restrict__ out, int n4) {
    for (int i = blockIdx.x * blockDim.x + threadIdx.x; i < n4;
         i += gridDim.x * blockDim.x) {
        float4 v = in[i];
        __half2 h0 = __floats2half2_rn(v.x, v.y);
        __half2 h1 = __floats2half2_rn(v.z, v.w);
        out[i] = make_uint2(*(uint32_t*)&h0, *(uint32_t*)&h1);
    }
}

__global__ __launch_bounds__(256) void transpose_f2h(
    const float* __restrict__ W, __half* __restrict__ WT, int K, int N)
{
    __shared__ float t[32][33];
    const int n0 = blockIdx.x * 32, k0 = blockIdx.y * 32;
    const int tx = threadIdx.x, ty = threadIdx.y;
    #pragma unroll
    for (int r = 0; r < 4; r++)
        t[ty + r * 8][tx] = W[(size_t)(k0 + ty + r * 8) * N + n0 + tx];
    __syncthreads();
    #pragma unroll
    for (int r = 0; r < 4; r++)
        WT[(size_t)(n0 + ty + r * 8) * K + k0 + tx] =
            __float2half_rn(t[tx][ty + r * 8]);
}

// ---------------------------------------------------------------------------
// fp16 HMMA GEMM v2: C[M,N] = A[M,K] @ BT[N,K]^T.
// 128x128 CTA tile, 4 warps (2x2), warp tile 64x64, BK=32, 4-stage cp.async.
// ---------------------------------------------------------------------------
#define GSTR 40
#define HG_STAGE (128 * GSTR)                    // halves per array per stage
#define HG_SMEM  (8 * HG_STAGE * 2)              // 4 stages * (A+B) = 81920 B

template<bool HALF_OUT>
__global__ __launch_bounds__(128) void hgemm(
    const __half* __restrict__ A, const __half* __restrict__ B,
    void* __restrict__ Cv, int N, int K)
{
    extern __shared__ __half hsm[];
    const uint32_t aBase = smem_u32(hsm);                       // stages 0..3 A
    const uint32_t bBase = aBase + 4 * HG_STAGE * 2;            // stages 0..3 B

    const int tid  = threadIdx.x;
    const int lane = tid & 31;
    const int wid  = tid >> 5;
    const int wm   = (wid >> 1) * 64;
    const int wn   = (wid & 1) * 64;
    const int bm   = blockIdx.y * 128;
    const int bn   = blockIdx.x * 128;

    const int mi = lane >> 3, r8 = lane & 7;
    const int fRowA = (mi & 1) * 8 + r8;
    const int fColA = (mi >> 1) * 8;
    const int fRowB = (mi >> 1) * 8 + r8;
    const int fColB = (mi & 1) * 8;

    float acc[4][8][4];
    #pragma unroll
    for (int i = 0; i < 4; i++)
        #pragma unroll
        for (int j = 0; j < 8; j++)
            #pragma unroll
            for (int r = 0; r < 4; r++) acc[i][j][r] = 0.0f;

    auto stage = [&](int s, int k0) {
        #pragma unroll
        for (int h = 0; h < 4; h++) {
            int idx = tid + 128 * h;          // 0..511
            int row = idx >> 2, c8 = (idx & 3) * 8;
            cp16(aBase + (uint32_t)(s * HG_STAGE + row * GSTR + c8) * 2,
                 A + (size_t)(bm + row) * K + k0 + c8);
            cp16(bBase + (uint32_t)(s * HG_STAGE + row * GSTR + c8) * 2,
                 B + (size_t)(bn + row) * K + k0 + c8);
        }
        CP_COMMIT();
    };

    const int NIT = K >> 5;                   // 64 for K=2048
    stage(0, 0); stage(1, 32); stage(2, 64);

    for (int i = 0; i < NIT; i++) {
        if (i + 3 < NIT) { stage((i + 3) & 3, (i + 3) << 5); CP_WAIT3(); }
        else {
            int rem = NIT - 1 - i;
            if (rem == 2)      CP_WAIT2();
            else if (rem == 1) CP_WAIT1();
            else               CP_WAIT0();
        }
        __syncthreads();

        const int s = i & 3;
        const uint32_t aS = aBase + (uint32_t)(s * HG_STAGE) * 2;
        const uint32_t bS = bBase + (uint32_t)(s * HG_STAGE) * 2;

        #pragma unroll
        for (int ks = 0; ks < 2; ks++) {
            uint32_t af[4][4], bf[4][4];
            #pragma unroll
            for (int mt = 0; mt < 4; mt++)
                ldm_x4(af[mt], aS + (uint32_t)((wm + mt * 16 + fRowA) * GSTR +
                                               ks * 16 + fColA) * 2);
            #pragma unroll
            for (int p = 0; p < 4; p++)
                ldm_x4(bf[p], bS + (uint32_t)((wn + p * 16 + fRowB) * GSTR +
                                              ks * 16 + fColB) * 2);
            #pragma unroll
            for (int mt = 0; mt < 4; mt++)
                #pragma unroll
                for (int p = 0; p < 4; p++) {
                    mma16816(acc[mt][2*p],   af[mt], bf[p][0], bf[p][1]);
                    mma16816(acc[mt][2*p+1], af[mt], bf[p][2], bf[p][3]);
                }
        }
        __syncthreads();
    }

    const int g = lane >> 2, t = lane & 3;
    #pragma unroll
    for (int mt = 0; mt < 4; mt++) {
        int row0 = bm + wm + mt * 16 + g;
        #pragma unroll
        for (int nt = 0; nt < 8; nt++) {
            int col = bn + wn + nt * 8 + 2 * t;
            if (HALF_OUT) {
                __half* C = (__half*)Cv;
                *(__half2*)&C[(size_t)row0 * N + col] =
                    __floats2half2_rn(acc[mt][nt][0], acc[mt][nt][1]);
                *(__half2*)&C[(size_t)(row0 + 8) * N + col] =
                    __floats2half2_rn(acc[mt][nt][2], acc[mt][nt][3]);
            } else {
                float* C = (float*)Cv;
                *(float2*)&C[(size_t)row0 * N + col] =
                    make_float2(acc[mt][nt][0], acc[mt][nt][1]);
                *(float2*)&C[(size_t)(row0 + 8) * N + col] =
                    make_float2(acc[mt][nt][2], acc[mt][nt][3]);
            }
        }
    }
}

// ---------------------------------------------------------------------------
// Flash attention v3: fp16 HMMA, P kept in registers (C-frag == A-frag trick),
// exp2-domain softmax. 128 threads = 4 warps; warp w owns q rows [16w,16w+16).
// Q/K/V from fused QKV buffer (row stride QKVN). Grid (S/64, NQH, BATCH).
// ---------------------------------------------------------------------------
#define KVSTR 72

__global__ __launch_bounds__(128) void flash_h3(
    const __half* __restrict__ QKV, __half* __restrict__ O)
{
    __shared__ __half Ks[2][64 * KVSTR];
    __shared__ __half Vs[2][64 * KVSTR];

    const int tid  = threadIdx.x;
    const int lane = tid & 31;
    const int wid  = tid >> 5;
    const int g    = lane >> 2;
    const int t    = lane & 3;
    const int qt   = blockIdx.x;
    const int qh   = blockIdx.y;
    const int b    = blockIdx.z;
    const int kvh  = qh >> 2;
    const float SCALE2 = 0.125f * 1.4426950408889634f;  // sm_scale * log2(e)

    const __half* Qg = QKV + ((size_t)(b * S_LEN + qt * 64)) * QKVN + qh * HD;
    const __half* Kg = QKV + ((size_t)b * S_LEN) * QKVN + 2048 + kvh * HD;
    const __half* Vg = QKV + ((size_t)b * S_LEN) * QKVN + 2560 + kvh * HD;
    __half*       Og = O + ((size_t)(b * S_LEN + qt * 64)) * DIM_ + qh * HD;

    const uint32_t ksBase = smem_u32(Ks);
    const uint32_t vsBase = smem_u32(Vs);

    const int mi = lane >> 3, r8 = lane & 7;
    const int aRow = (mi & 1) * 8 + r8;
    const int aCol = (mi >> 1) * 8;
    const int bRow = (mi >> 1) * 8 + r8;
    const int bCol = (mi & 1) * 8;

    // --- Stage Q into Ks[0], grab Q fragments ---
    #pragma unroll
    for (int h = 0; h < 4; h++) {
        int idx = tid + 128 * h;
        int row = idx >> 3, c8 = (idx & 7) * 8;
        *(uint4*)&Ks[0][row * KVSTR + c8] =
            *(const uint4*)&Qg[(size_t)row * QKVN + c8];
    }
    __syncthreads();

    uint32_t qf[4][4];
    {
        const int m0 = wid * 16;
        #pragma unroll
        for (int ks = 0; ks < 4; ks++)
            ldm_x4(qf[ks], ksBase + (uint32_t)((m0 + aRow) * KVSTR +
                                               ks * 16 + aCol) * 2);
    }
    __syncthreads();

    auto stage = [&](int s, int kt) {
        const __half* kg = Kg + (size_t)(kt * 64) * QKVN;
        const __half* vg = Vg + (size_t)(kt * 64) * QKVN;
        #pragma unroll
        for (int h = 0; h < 4; h++) {
            int idx = tid + 128 * h;
            int row = idx >> 3, c8 = (idx & 7) * 8;
            uint32_t so = (uint32_t)(s * 64 * KVSTR + row * KVSTR + c8) * 2;
            cp16(ksBase + so, kg + (size_t)row * QKVN + c8);
            cp16(vsBase + so, vg + (size_t)row * QKVN + c8);
        }
        CP_COMMIT();
    };

    float m0r = -1e30f, m1r = -1e30f, l0r = 0.0f, l1r = 0.0f;
    float oacc[8][4];
    #pragma unroll
    for (int j = 0; j < 8; j++)
        #pragma unroll
        for (int r = 0; r < 4; r++) oacc[j][r] = 0.0f;

    const int NC = S_LEN / 64;
    stage(0, 0);
    for (int kt = 0; kt < NC; kt++) {
        if (kt + 1 < NC) { stage((kt + 1) & 1, kt + 1); CP_WAIT1(); }
        else             { CP_WAIT0(); }
        __syncthreads();

        const int s = kt & 1;
        const uint32_t ksB = ksBase + (uint32_t)(s * 64 * KVSTR) * 2;
        const uint32_t vsB = vsBase + (uint32_t)(s * 64 * KVSTR) * 2;

        // --- S = Q @ K^T ---
        float sacc[8][4];
        #pragma unroll
        for (int nt = 0; nt < 8; nt++)
            #pragma unroll
            for (int r = 0; r < 4; r++) sacc[nt][r] = 0.0f;

        #pragma unroll
        for (int ks = 0; ks < 4; ks++) {
            #pragma unroll
            for (int p = 0; p < 4; p++) {
                uint32_t rr[4];
                ldm_x4(rr, ksB + (uint32_t)((p * 16 + bRow) * KVSTR +
                                            ks * 16 + bCol) * 2);
                mma16816(sacc[2*p],   qf[ks], rr[0], rr[1]);
                mma16816(sacc[2*p+1], qf[ks], rr[2], rr[3]);
            }
        }

        // --- Online softmax (exp2 domain) ---
        float mx0 = -1e30f, mx1 = -1e30f;
        #pragma unroll
        for (int nt = 0; nt < 8; nt++) {
            sacc[nt][0] *= SCALE2; sacc[nt][1] *= SCALE2;
            sacc[nt][2] *= SCALE2; sacc[nt][3] *= SCALE2;
            mx0 = fmaxf(mx0, fmaxf(sacc[nt][0], sacc[nt][1]));
            mx1 = fmaxf(mx1, fmaxf(sacc[nt][2], sacc[nt][3]));
        }
        mx0 = fmaxf(mx0, __shfl_xor_sync(0xffffffffu, mx0, 1));
        mx0 = fmaxf(mx0, __shfl_xor_sync(0xffffffffu, mx0, 2));
        mx1 = fmaxf(mx1, __shfl_xor_sync(0xffffffffu, mx1, 1));
        mx1 = fmaxf(mx1, __shfl_xor_sync(0xffffffffu, mx1, 2));

        float mn0 = fmaxf(m0r, mx0), mn1 = fmaxf(m1r, mx1);
        float a0 = exp2f(m0r - mn0), a1 = exp2f(m1r - mn1);
        m0r = mn0; m1r = mn1;

        float s0 = 0.0f, s1 = 0.0f;
        #pragma unroll
        for (int nt = 0; nt < 8; nt++) {
            sacc[nt][0] = exp2f(sacc[nt][0] - mn0);
            sacc[nt][1] = exp2f(sacc[nt][1] - mn0);
            sacc[nt][2] = exp2f(sacc[nt][2] - mn1);
            sacc[nt][3] = exp2f(sacc[nt][3] - mn1);
            s0 += sacc[nt][0] + sacc[nt][1];
            s1 += sacc[nt][2] + sacc[nt][3];
        }
        s0 += __shfl_xor_sync(0xffffffffu, s0, 1);
        s0 += __shfl_xor_sync(0xffffffffu, s0, 2);
        s1 += __shfl_xor_sync(0xffffffffu, s1, 1);
        s1 += __shfl_xor_sync(0xffffffffu, s1, 2);
        l0r = l0r * a0 + s0;
        l1r = l1r * a1 + s1;

        // --- P -> A fragments directly in registers (C-frag == A-frag) ---
        uint32_t pf[4][4];
        #pragma unroll
        for (int ks = 0; ks < 4; ks++) {
            pf[ks][0] = h2u(sacc[2*ks][0],   sacc[2*ks][1]);
            pf[ks][1] = h2u(sacc[2*ks][2],   sacc[2*ks][3]);
            pf[ks][2] = h2u(sacc[2*ks+1][0], sacc[2*ks+1][1]);
            pf[ks][3] = h2u(sacc[2*ks+1][2], sacc[2*ks+1][3]);
        }

        #pragma unroll
        for (int j = 0; j < 8; j++) {
            oacc[j][0] *= a0; oacc[j][1] *= a0;
            oacc[j][2] *= a1; oacc[j][3] *= a1;
        }

        // --- O += P @ V ---
        #pragma unroll
        for (int ks = 0; ks < 4; ks++) {
            #pragma unroll
            for (int p = 0; p < 4; p++) {
                uint32_t rr[4];
                ldm_x4_trans(rr, vsB + (uint32_t)((ks * 16 + aRow) * KVSTR +
                                                  p * 16 + aCol) * 2);
                mma16816(oacc[2*p],   pf[ks], rr[0], rr[1]);
                mma16816(oacc[2*p+1], pf[ks], rr[2], rr[3]);
            }
        }
        __syncthreads();
    }

    // --- Normalize and write out (half) ---
    float inv0 = 1.0f / l0r, inv1 = 1.0f / l1r;
    int qrow0 = wid * 16 + g;
    #pragma unroll
    for (int j = 0; j < 8; j++) {
        int col = j * 8 + 2 * t;
        *(__half2*)&Og[(size_t)qrow0 * DIM_ + col] =
            __floats2half2_rn(oacc[j][0] * inv0, oacc[j][1] * inv0);
        *(__half2*)&Og[(size_t)(qrow0 + 8) * DIM_ + col] =
            __floats2half2_rn(oacc[j][2] * inv1, oacc[j][3] * inv1);
    }
}

// ---------------------------------------------------------------------------
// Launch
// ---------------------------------------------------------------------------
extern "C" void kernel_launch(void* const* d_in, const int* in_sizes, int n_in,
                              void* d_out, int out_size) {
    (void)in_sizes; (void)n_in; (void)out_size;
    const float* x  = (const float*)d_in[0];
    const float* Wq = (const float*)d_in[1];
    const float* Wk = (const float*)d_in[2];
    const float* Wv = (const float*)d_in[3];
    const float* Wo = (const float*)d_in[4];
    float* out = (float*)d_out;

    __half *xh, *Wqkv, *WoT, *QKVh, *Oh;
    cudaGetSymbolAddress((void**)&xh,   g_xh);
    cudaGetSymbolAddress((void**)&Wqkv, g_Wqkv);
    cudaGetSymbolAddress((void**)&WoT,  g_WoT);
    cudaGetSymbolAddress((void**)&QKVh, g_QKV);
    cudaGetSymbolAddress((void**)&Oh,   g_Oh);

    cudaFuncSetAttribute(hgemm<true>,
        cudaFuncAttributeMaxDynamicSharedMemorySize, HG_SMEM);
    cudaFuncSetAttribute(hgemm<false>,
        cudaFuncAttributeMaxDynamicSharedMemorySize, HG_SMEM);

    dim3 tb(32, 8);
    f2h_kernel<<<1024, 256>>>((const float4*)x, (uint2*)xh,
                              (M_ROWS * DIM_) / 4);
    transpose_f2h<<<dim3(DIM_ / 32,  DIM_ / 32), tb>>>(Wq, Wqkv, DIM_, DIM_);
    transpose_f2h<<<dim3(KVDIM / 32, DIM_ / 32), tb>>>(
        Wk, Wqkv + (size_t)2048 * DIM_, DIM_, KVDIM);
    transpose_f2h<<<dim3(KVDIM / 32, DIM_ / 32), tb>>>(
        Wv, Wqkv + (size_t)2560 * DIM_, DIM_, KVDIM);
    transpose_f2h<<<dim3(DIM_ / 32,  DIM_ / 32), tb>>>(Wo, WoT, DIM_, DIM_);

    // Fused QKV projection
    hgemm<true><<<dim3(QKVN / 128, M_ROWS / 128), 128, HG_SMEM>>>(
        xh, Wqkv, QKVh, QKVN, DIM_);

    // Attention
    flash_h3<<<dim3(S_LEN / 64, NQH, BATCH), 128>>>(QKVh, Oh);

    // Output projection (fp32 out)
    hgemm<false><<<dim3(DIM_ / 128, M_ROWS / 128), 128, HG_SMEM>>>(
        Oh, WoT, out, DIM_, DIM_);
}

// round 7
// speedup vs baseline: 10.6397x; 1.0280x over previous
#include <cuda_runtime.h>
#include <cuda_fp16.h>
#include <math.h>
#include <stdint.h>

// Problem constants
#define BATCH   2
#define S_LEN   2048
#define DIM_    2048
#define KVDIM   512
#define QKVN    3072
#define HD      64
#define NQH     32
#define M_ROWS  (BATCH * S_LEN)   // 4096

// ---------------------------------------------------------------------------
// Scratch
// ---------------------------------------------------------------------------
__device__ __half g_xh  [(size_t)M_ROWS * DIM_];
__device__ __half g_Wqkv[(size_t)QKVN * DIM_];   // [N,K] half
__device__ __half g_WoT [(size_t)DIM_ * DIM_];
__device__ __half g_QKV [(size_t)M_ROWS * QKVN];
__device__ __half g_Oh  [(size_t)M_ROWS * DIM_];

// ---------------------------------------------------------------------------
// Helpers
// ---------------------------------------------------------------------------
__device__ __forceinline__ uint32_t smem_u32(const void* p) {
    uint32_t a;
    asm("{ .reg .u64 t; cvta.to.shared.u64 t, %1; cvt.u32.u64 %0, t; }"
        : "=r"(a) : "l"(p));
    return a;
}

__device__ __forceinline__ void ldm_x4(uint32_t r[4], uint32_t addr) {
    asm volatile("ldmatrix.sync.aligned.m8n8.x4.shared.b16 {%0,%1,%2,%3}, [%4];"
        : "=r"(r[0]), "=r"(r[1]), "=r"(r[2]), "=r"(r[3]) : "r"(addr));
}

__device__ __forceinline__ void ldm_x4_trans(uint32_t r[4], uint32_t addr) {
    asm volatile("ldmatrix.sync.aligned.m8n8.x4.trans.shared.b16 {%0,%1,%2,%3}, [%4];"
        : "=r"(r[0]), "=r"(r[1]), "=r"(r[2]), "=r"(r[3]) : "r"(addr));
}

__device__ __forceinline__ void mma16816(float c[4], const uint32_t a[4],
                                         uint32_t b0, uint32_t b1) {
    asm volatile(
        "mma.sync.aligned.m16n8k16.row.col.f32.f16.f16.f32 "
        "{%0,%1,%2,%3}, {%4,%5,%6,%7}, {%8,%9}, {%0,%1,%2,%3};"
        : "+f"(c[0]), "+f"(c[1]), "+f"(c[2]), "+f"(c[3])
        : "r"(a[0]), "r"(a[1]), "r"(a[2]), "r"(a[3]), "r"(b0), "r"(b1));
}

__device__ __forceinline__ void cp16(uint32_t dst, const void* src) {
    asm volatile("cp.async.cg.shared.global [%0], [%1], 16;"
        :: "r"(dst), "l"(src));
}
#define CP_COMMIT() asm volatile("cp.async.commit_group;")
#define CP_WAIT0()  asm volatile("cp.async.wait_group 0;")
#define CP_WAIT1()  asm volatile("cp.async.wait_group 1;")
#define CP_WAIT2()  asm volatile("cp.async.wait_group 2;")
#define CP_WAIT3()  asm volatile("cp.async.wait_group 3;")

__device__ __forceinline__ uint32_t h2u(float a, float b) {
    __half2 h = __floats2half2_rn(a, b);
    return *(uint32_t*)&h;
}

// ---------------------------------------------------------------------------
// Prep kernels
// ---------------------------------------------------------------------------
__global__ void f2h_kernel(const float4* __restrict__ in,
                           uint2* __restrict__ out, int n4) {
    for (int i = blockIdx.x * blockDim.x + threadIdx.x; i < n4;
         i += gridDim.x * blockDim.x) {
        float4 v = in[i];
        __half2 h0 = __floats2half2_rn(v.x, v.y);
        __half2 h1 = __floats2half2_rn(v.z, v.w);
        out[i] = make_uint2(*(uint32_t*)&h0, *(uint32_t*)&h1);
    }
}

__global__ __launch_bounds__(256) void transpose_f2h(
    const float* __restrict__ W, __half* __restrict__ WT, int K, int N)
{
    __shared__ float t[32][33];
    const int n0 = blockIdx.x * 32, k0 = blockIdx.y * 32;
    const int tx = threadIdx.x, ty = threadIdx.y;
    #pragma unroll
    for (int r = 0; r < 4; r++)
        t[ty + r * 8][tx] = W[(size_t)(k0 + ty + r * 8) * N + n0 + tx];
    __syncthreads();
    #pragma unroll
    for (int r = 0; r < 4; r++)
        WT[(size_t)(n0 + ty + r * 8) * K + k0 + tx] =
            __float2half_rn(t[tx][ty + r * 8]);
}

// ---------------------------------------------------------------------------
// fp16 HMMA GEMM v2 (unchanged from R6): 128x128 CTA, 4 warps, 64x64 warp
// tiles, BK=32, 4-stage cp.async.
// ---------------------------------------------------------------------------
#define GSTR 40
#define HG_STAGE (128 * GSTR)
#define HG_SMEM  (8 * HG_STAGE * 2)              // 81920 B

template<bool HALF_OUT>
__global__ __launch_bounds__(128) void hgemm(
    const __half* __restrict__ A, const __half* __restrict__ B,
    void* __restrict__ Cv, int N, int K)
{
    extern __shared__ __half hsm[];
    const uint32_t aBase = smem_u32(hsm);
    const uint32_t bBase = aBase + 4 * HG_STAGE * 2;

    const int tid  = threadIdx.x;
    const int lane = tid & 31;
    const int wid  = tid >> 5;
    const int wm   = (wid >> 1) * 64;
    const int wn   = (wid & 1) * 64;
    const int bm   = blockIdx.y * 128;
    const int bn   = blockIdx.x * 128;

    const int mi = lane >> 3, r8 = lane & 7;
    const int fRowA = (mi & 1) * 8 + r8;
    const int fColA = (mi >> 1) * 8;
    const int fRowB = (mi >> 1) * 8 + r8;
    const int fColB = (mi & 1) * 8;

    float acc[4][8][4];
    #pragma unroll
    for (int i = 0; i < 4; i++)
        #pragma unroll
        for (int j = 0; j < 8; j++)
            #pragma unroll
            for (int r = 0; r < 4; r++) acc[i][j][r] = 0.0f;

    auto stage = [&](int s, int k0) {
        #pragma unroll
        for (int h = 0; h < 4; h++) {
            int idx = tid + 128 * h;
            int row = idx >> 2, c8 = (idx & 3) * 8;
            cp16(aBase + (uint32_t)(s * HG_STAGE + row * GSTR + c8) * 2,
                 A + (size_t)(bm + row) * K + k0 + c8);
            cp16(bBase + (uint32_t)(s * HG_STAGE + row * GSTR + c8) * 2,
                 B + (size_t)(bn + row) * K + k0 + c8);
        }
        CP_COMMIT();
    };

    const int NIT = K >> 5;
    stage(0, 0); stage(1, 32); stage(2, 64);

    for (int i = 0; i < NIT; i++) {
        if (i + 3 < NIT) { stage((i + 3) & 3, (i + 3) << 5); CP_WAIT3(); }
        else {
            int rem = NIT - 1 - i;
            if (rem == 2)      CP_WAIT2();
            else if (rem == 1) CP_WAIT1();
            else               CP_WAIT0();
        }
        __syncthreads();

        const int s = i & 3;
        const uint32_t aS = aBase + (uint32_t)(s * HG_STAGE) * 2;
        const uint32_t bS = bBase + (uint32_t)(s * HG_STAGE) * 2;

        #pragma unroll
        for (int ks = 0; ks < 2; ks++) {
            uint32_t af[4][4], bf[4][4];
            #pragma unroll
            for (int mt = 0; mt < 4; mt++)
                ldm_x4(af[mt], aS + (uint32_t)((wm + mt * 16 + fRowA) * GSTR +
                                               ks * 16 + fColA) * 2);
            #pragma unroll
            for (int p = 0; p < 4; p++)
                ldm_x4(bf[p], bS + (uint32_t)((wn + p * 16 + fRowB) * GSTR +
                                              ks * 16 + fColB) * 2);
            #pragma unroll
            for (int mt = 0; mt < 4; mt++)
                #pragma unroll
                for (int p = 0; p < 4; p++) {
                    mma16816(acc[mt][2*p],   af[mt], bf[p][0], bf[p][1]);
                    mma16816(acc[mt][2*p+1], af[mt], bf[p][2], bf[p][3]);
                }
        }
        __syncthreads();
    }

    const int g = lane >> 2, t = lane & 3;
    #pragma unroll
    for (int mt = 0; mt < 4; mt++) {
        int row0 = bm + wm + mt * 16 + g;
        #pragma unroll
        for (int nt = 0; nt < 8; nt++) {
            int col = bn + wn + nt * 8 + 2 * t;
            if (HALF_OUT) {
                __half* C = (__half*)Cv;
                *(__half2*)&C[(size_t)row0 * N + col] =
                    __floats2half2_rn(acc[mt][nt][0], acc[mt][nt][1]);
                *(__half2*)&C[(size_t)(row0 + 8) * N + col] =
                    __floats2half2_rn(acc[mt][nt][2], acc[mt][nt][3]);
            } else {
                float* C = (float*)Cv;
                *(float2*)&C[(size_t)row0 * N + col] =
                    make_float2(acc[mt][nt][0], acc[mt][nt][1]);
                *(float2*)&C[(size_t)(row0 + 8) * N + col] =
                    make_float2(acc[mt][nt][2], acc[mt][nt][3]);
            }
        }
    }
}

// ---------------------------------------------------------------------------
// Flash attention v4: fp16 HMMA, 2 m-tiles per warp (32 q-rows/warp,
// 128 q-rows/CTA), P in registers, exp2-domain softmax.
// 128 threads = 4 warps. Grid (S/128, NQH, BATCH).
// ---------------------------------------------------------------------------
#define KVSTR 72

__global__ __launch_bounds__(128) void flash_h4(
    const __half* __restrict__ QKV, __half* __restrict__ O)
{
    __shared__ __half Ks[2][64 * KVSTR];   // also Q staging (128 rows total)
    __shared__ __half Vs[2][64 * KVSTR];

    const int tid  = threadIdx.x;
    const int lane = tid & 31;
    const int wid  = tid >> 5;
    const int g    = lane >> 2;
    const int t    = lane & 3;
    const int qt   = blockIdx.x;
    const int qh   = blockIdx.y;
    const int b    = blockIdx.z;
    const int kvh  = qh >> 2;
    const float SCALE2 = 0.125f * 1.4426950408889634f;

    const __half* Qg = QKV + ((size_t)(b * S_LEN + qt * 128)) * QKVN + qh * HD;
    const __half* Kg = QKV + ((size_t)b * S_LEN) * QKVN + 2048 + kvh * HD;
    const __half* Vg = QKV + ((size_t)b * S_LEN) * QKVN + 2560 + kvh * HD;
    __half*       Og = O + ((size_t)(b * S_LEN + qt * 128)) * DIM_ + qh * HD;

    const uint32_t ksBase = smem_u32(Ks);
    const uint32_t vsBase = smem_u32(Vs);

    const int mi = lane >> 3, r8 = lane & 7;
    const int aRow = (mi & 1) * 8 + r8;
    const int aCol = (mi >> 1) * 8;
    const int bRow = (mi >> 1) * 8 + r8;
    const int bCol = (mi & 1) * 8;

    // --- Stage Q (128 rows x 64) across Ks[0..1], grab Q fragments ---
    #pragma unroll
    for (int h = 0; h < 8; h++) {
        int idx = tid + 128 * h;              // 0..1023 uint4
        int row = idx >> 3, c8 = (idx & 7) * 8;
        *(uint4*)&Ks[0][row * KVSTR + c8] =
            *(const uint4*)&Qg[(size_t)row * QKVN + c8];
    }
    __syncthreads();

    uint32_t qf[2][4][4];
    #pragma unroll
    for (int mt = 0; mt < 2; mt++) {
        const int m0 = wid * 32 + mt * 16;
        #pragma unroll
        for (int ks = 0; ks < 4; ks++)
            ldm_x4(qf[mt][ks], ksBase + (uint32_t)((m0 + aRow) * KVSTR +
                                                   ks * 16 + aCol) * 2);
    }
    __syncthreads();

    auto stage = [&](int s, int kt) {
        const __half* kg = Kg + (size_t)(kt * 64) * QKVN;
        const __half* vg = Vg + (size_t)(kt * 64) * QKVN;
        #pragma unroll
        for (int h = 0; h < 4; h++) {
            int idx = tid + 128 * h;
            int row = idx >> 3, c8 = (idx & 7) * 8;
            uint32_t so = (uint32_t)(s * 64 * KVSTR + row * KVSTR + c8) * 2;
            cp16(ksBase + so, kg + (size_t)row * QKVN + c8);
            cp16(vsBase + so, vg + (size_t)row * QKVN + c8);
        }
        CP_COMMIT();
    };

    float mr[2][2], lr[2][2];
    #pragma unroll
    for (int mt = 0; mt < 2; mt++) {
        mr[mt][0] = mr[mt][1] = -1e30f;
        lr[mt][0] = lr[mt][1] = 0.0f;
    }
    float oacc[2][8][4];
    #pragma unroll
    for (int mt = 0; mt < 2; mt++)
        #pragma unroll
        for (int j = 0; j < 8; j++)
            #pragma unroll
            for (int r = 0; r < 4; r++) oacc[mt][j][r] = 0.0f;

    const int NC = S_LEN / 64;
    stage(0, 0);
    for (int kt = 0; kt < NC; kt++) {
        if (kt + 1 < NC) { stage((kt + 1) & 1, kt + 1); CP_WAIT1(); }
        else             { CP_WAIT0(); }
        __syncthreads();

        const int s = kt & 1;
        const uint32_t ksB = ksBase + (uint32_t)(s * 64 * KVSTR) * 2;
        const uint32_t vsB = vsBase + (uint32_t)(s * 64 * KVSTR) * 2;

        // --- S = Q @ K^T (both m-tiles share each K fragment) ---
        float sacc[2][8][4];
        #pragma unroll
        for (int mt = 0; mt < 2; mt++)
            #pragma unroll
            for (int nt = 0; nt < 8; nt++)
                #pragma unroll
                for (int r = 0; r < 4; r++) sacc[mt][nt][r] = 0.0f;

        #pragma unroll
        for (int ks = 0; ks < 4; ks++) {
            #pragma unroll
            for (int p = 0; p < 4; p++) {
                uint32_t rr[4];
                ldm_x4(rr, ksB + (uint32_t)((p * 16 + bRow) * KVSTR +
                                            ks * 16 + bCol) * 2);
                #pragma unroll
                for (int mt = 0; mt < 2; mt++) {
                    mma16816(sacc[mt][2*p],   qf[mt][ks], rr[0], rr[1]);
                    mma16816(sacc[mt][2*p+1], qf[mt][ks], rr[2], rr[3]);
                }
            }
        }

        // --- Online softmax per m-tile; P -> A-fragments in registers ---
        uint32_t pf[2][4][4];
        float alpha[2][2];
        #pragma unroll
        for (int mt = 0; mt < 2; mt++) {
            float mx0 = -1e30f, mx1 = -1e30f;
            #pragma unroll
            for (int nt = 0; nt < 8; nt++) {
                sacc[mt][nt][0] *= SCALE2; sacc[mt][nt][1] *= SCALE2;
                sacc[mt][nt][2] *= SCALE2; sacc[mt][nt][3] *= SCALE2;
                mx0 = fmaxf(mx0, fmaxf(sacc[mt][nt][0], sacc[mt][nt][1]));
                mx1 = fmaxf(mx1, fmaxf(sacc[mt][nt][2], sacc[mt][nt][3]));
            }
            mx0 = fmaxf(mx0, __shfl_xor_sync(0xffffffffu, mx0, 1));
            mx0 = fmaxf(mx0, __shfl_xor_sync(0xffffffffu, mx0, 2));
            mx1 = fmaxf(mx1, __shfl_xor_sync(0xffffffffu, mx1, 1));
            mx1 = fmaxf(mx1, __shfl_xor_sync(0xffffffffu, mx1, 2));

            float mn0 = fmaxf(mr[mt][0], mx0), mn1 = fmaxf(mr[mt][1], mx1);
            alpha[mt][0] = exp2f(mr[mt][0] - mn0);
            alpha[mt][1] = exp2f(mr[mt][1] - mn1);
            mr[mt][0] = mn0; mr[mt][1] = mn1;

            float s0 = 0.0f, s1 = 0.0f;
            #pragma unroll
            for (int nt = 0; nt < 8; nt++) {
                sacc[mt][nt][0] = exp2f(sacc[mt][nt][0] - mn0);
                sacc[mt][nt][1] = exp2f(sacc[mt][nt][1] - mn0);
                sacc[mt][nt][2] = exp2f(sacc[mt][nt][2] - mn1);
                sacc[mt][nt][3] = exp2f(sacc[mt][nt][3] - mn1);
                s0 += sacc[mt][nt][0] + sacc[mt][nt][1];
                s1 += sacc[mt][nt][2] + sacc[mt][nt][3];
            }
            s0 += __shfl_xor_sync(0xffffffffu, s0, 1);
            s0 += __shfl_xor_sync(0xffffffffu, s0, 2);
            s1 += __shfl_xor_sync(0xffffffffu, s1, 1);
            s1 += __shfl_xor_sync(0xffffffffu, s1, 2);
            lr[mt][0] = lr[mt][0] * alpha[mt][0] + s0;
            lr[mt][1] = lr[mt][1] * alpha[mt][1] + s1;

            #pragma unroll
            for (int ks = 0; ks < 4; ks++) {
                pf[mt][ks][0] = h2u(sacc[mt][2*ks][0],   sacc[mt][2*ks][1]);
                pf[mt][ks][1] = h2u(sacc[mt][2*ks][2],   sacc[mt][2*ks][3]);
                pf[mt][ks][2] = h2u(sacc[mt][2*ks+1][0], sacc[mt][2*ks+1][1]);
                pf[mt][ks][3] = h2u(sacc[mt][2*ks+1][2], sacc[mt][2*ks+1][3]);
            }
            #pragma unroll
            for (int j = 0; j < 8; j++) {
                oacc[mt][j][0] *= alpha[mt][0]; oacc[mt][j][1] *= alpha[mt][0];
                oacc[mt][j][2] *= alpha[mt][1]; oacc[mt][j][3] *= alpha[mt][1];
            }
        }

        // --- O += P @ V (both m-tiles share each V fragment) ---
        #pragma unroll
        for (int ks = 0; ks < 4; ks++) {
            #pragma unroll
            for (int p = 0; p < 4; p++) {
                uint32_t rr[4];
                ldm_x4_trans(rr, vsB + (uint32_t)((ks * 16 + aRow) * KVSTR +
                                                  p * 16 + aCol) * 2);
                #pragma unroll
                for (int mt = 0; mt < 2; mt++) {
                    mma16816(oacc[mt][2*p],   pf[mt][ks], rr[0], rr[1]);
                    mma16816(oacc[mt][2*p+1], pf[mt][ks], rr[2], rr[3]);
                }
            }
        }
        __syncthreads();
    }

    // --- Normalize and write out (half) ---
    #pragma unroll
    for (int mt = 0; mt < 2; mt++) {
        float inv0 = 1.0f / lr[mt][0], inv1 = 1.0f / lr[mt][1];
        int qrow0 = wid * 32 + mt * 16 + g;
        #pragma unroll
        for (int j = 0; j < 8; j++) {
            int col = j * 8 + 2 * t;
            *(__half2*)&Og[(size_t)qrow0 * DIM_ + col] =
                __floats2half2_rn(oacc[mt][j][0] * inv0, oacc[mt][j][1] * inv0);
            *(__half2*)&Og[(size_t)(qrow0 + 8) * DIM_ + col] =
                __floats2half2_rn(oacc[mt][j][2] * inv1, oacc[mt][j][3] * inv1);
        }
    }
}

// ---------------------------------------------------------------------------
// Launch
// ---------------------------------------------------------------------------
extern "C" void kernel_launch(void* const* d_in, const int* in_sizes, int n_in,
                              void* d_out, int out_size) {
    (void)in_sizes; (void)n_in; (void)out_size;
    const float* x  = (const float*)d_in[0];
    const float* Wq = (const float*)d_in[1];
    const float* Wk = (const float*)d_in[2];
    const float* Wv = (const float*)d_in[3];
    const float* Wo = (const float*)d_in[4];
    float* out = (float*)d_out;

    __half *xh, *Wqkv, *WoT, *QKVh, *Oh;
    cudaGetSymbolAddress((void**)&xh,   g_xh);
    cudaGetSymbolAddress((void**)&Wqkv, g_Wqkv);
    cudaGetSymbolAddress((void**)&WoT,  g_WoT);
    cudaGetSymbolAddress((void**)&QKVh, g_QKV);
    cudaGetSymbolAddress((void**)&Oh,   g_Oh);

    cudaFuncSetAttribute(hgemm<true>,
        cudaFuncAttributeMaxDynamicSharedMemorySize, HG_SMEM);
    cudaFuncSetAttribute(hgemm<false>,
        cudaFuncAttributeMaxDynamicSharedMemorySize, HG_SMEM);

    dim3 tb(32, 8);
    f2h_kernel<<<1024, 256>>>((const float4*)x, (uint2*)xh,
                              (M_ROWS * DIM_) / 4);
    transpose_f2h<<<dim3(DIM_ / 32,  DIM_ / 32), tb>>>(Wq, Wqkv, DIM_, DIM_);
    transpose_f2h<<<dim3(KVDIM / 32, DIM_ / 32), tb>>>(
        Wk, Wqkv + (size_t)2048 * DIM_, DIM_, KVDIM);
    transpose_f2h<<<dim3(KVDIM / 32, DIM_ / 32), tb>>>(
        Wv, Wqkv + (size_t)2560 * DIM_, DIM_, KVDIM);
    transpose_f2h<<<dim3(DIM_ / 32,  DIM_ / 32), tb>>>(Wo, WoT, DIM_, DIM_);

    // Fused QKV projection
    hgemm<true><<<dim3(QKVN / 128, M_ROWS / 128), 128, HG_SMEM>>>(
        xh, Wqkv, QKVh, QKVN, DIM_);

    // Attention (128 q-rows per CTA)
    flash_h4<<<dim3(S_LEN / 128, NQH, BATCH), 128>>>(QKVh, Oh);

    // Output projection (fp32 out)
    hgemm<false><<<dim3(DIM_ / 128, M_ROWS / 128), 128, HG_SMEM>>>(
        Oh, WoT, out, DIM_, DIM_);
}